// round 7
// baseline (speedup 1.0000x reference)
#include <cuda_runtime.h>
#include <cuda_fp16.h>
#include <math.h>
#include <cstdint>

#define BSZ  4
#define TSEQ 2048
#define CDIM 1024
#define MTOT (BSZ*TSEQ)

#define KC 32
#define LDP 40                         // padded row length (halfs)
#define SA_BYTES (128*LDP*2)           // 10240
#define SB_BYTES (256*LDP*2)           // 20480
#define SMEM_DYN (2*SA_BYTES + 2*SB_BYTES)   // 61440

// ------------------------- persistent scratch ------------------------------
__device__ __align__(16) __half g_X16[(size_t)MTOT*CDIM];
__device__ __align__(16) __half g_Wq16[(size_t)CDIM*CDIM];
__device__ __align__(16) __half g_Wk16[(size_t)CDIM*CDIM];
__device__ __align__(16) __half g_Wv16[(size_t)CDIM*CDIM];
__device__ __align__(16) __half g_Wf16[(size_t)CDIM*CDIM];
__device__ __align__(16) __half g_Q16[(size_t)MTOT*CDIM];
__device__ __align__(16) __half g_K16[(size_t)MTOT*CDIM];
__device__ __align__(16) float  g_V  [(size_t)MTOT*CDIM];
__device__ __align__(16) __half g_Vt [(size_t)BSZ*CDIM*TSEQ];
__device__ __align__(16) float  g_S  [(size_t)BSZ*TSEQ*TSEQ];
__device__ __align__(16) __half g_P  [(size_t)BSZ*TSEQ*TSEQ];
__device__ __align__(16) __half g_O16[(size_t)MTOT*CDIM];
__device__ __align__(16) float2 g_CS [(size_t)TSEQ*(CDIM/2)];

// ------------------------------ ptx helpers --------------------------------
__device__ __forceinline__ uint32_t smem_u32(const void* p) {
    uint32_t a;
    asm("{ .reg .u64 t; cvta.to.shared.u64 t, %1; cvt.u32.u64 %0, t; }"
        : "=r"(a) : "l"(p));
    return a;
}
__device__ __forceinline__ void cp16(uint32_t dst, const void* src) {
    asm volatile("cp.async.cg.shared.global [%0], [%1], 16;" :: "r"(dst), "l"(src));
}
#define CP_COMMIT() asm volatile("cp.async.commit_group;")
#define CP_WAIT0()  asm volatile("cp.async.wait_group 0;")
#define CP_WAIT1()  asm volatile("cp.async.wait_group 1;")

__device__ __forceinline__ void ldm_x4(uint32_t* r, uint32_t addr) {
    asm volatile("ldmatrix.sync.aligned.m8n8.x4.shared.b16 {%0,%1,%2,%3}, [%4];"
                 : "=r"(r[0]), "=r"(r[1]), "=r"(r[2]), "=r"(r[3]) : "r"(addr));
}
__device__ __forceinline__ void mma16816h(float* c, const uint32_t* a, const uint32_t* b) {
    asm volatile("mma.sync.aligned.m16n8k16.row.col.f32.f16.f16.f32 "
                 "{%0,%1,%2,%3}, {%4,%5,%6,%7}, {%8,%9}, {%0,%1,%2,%3};"
                 : "+f"(c[0]), "+f"(c[1]), "+f"(c[2]), "+f"(c[3])
                 : "r"(a[0]), "r"(a[1]), "r"(a[2]), "r"(a[3]), "r"(b[0]), "r"(b[1]));
}
__device__ __forceinline__ uint32_t pack_h2(float x, float y) {
    __half2 h = __floats2half2_rn(x, y);
    return *(uint32_t*)&h;
}

// ---------------------------------------------------------------------------
// fp16 NT GEMM, 128x256 CTA tile, 8 warps (2x4) of 64x64 warp tiles.
// C[m,n] = scale*sum_k A[m,k]*B[n,k] (+bias, +RoPE). fp32 accumulate.
// CMODE: 0 none, 1 causal tile-skip, 2 causal k-limit.
// OUT16: 1 -> fp16 out, 0 -> fp32 out.
// ---------------------------------------------------------------------------
template<int ROPE, int CMODE, int OUT16>
__global__ void __launch_bounds__(256, 1) gemm_h(
    const __half* __restrict__ A, const __half* __restrict__ B,
    const float* __restrict__ bias, const float2* __restrict__ cs,
    float* __restrict__ Cf, __half* __restrict__ Ch,
    int N, int K, long sA, long sB, long sC, float scale)
{
    int m0 = blockIdx.y * 128, n0 = blockIdx.x * 256;
    if (CMODE == 1 && n0 > m0 + 127) return;
    long z = blockIdx.z;
    A += z * sA; B += z * sB;
    if (OUT16) Ch += z * sC; else Cf += z * sC;

    extern __shared__ __align__(16) char smem_raw[];
    uint32_t a_s = smem_u32(smem_raw);                 // As: 2 x 128 x LDP
    uint32_t b_s = a_s + 2 * SA_BYTES;                 // Bs: 2 x 256 x LDP

    int tid = threadIdx.x, lane = tid & 31, wid = tid >> 5;
    int wm = wid & 1, wn = wid >> 1;                   // warp tile (wm*64, wn*64)

    int kmax = (CMODE == 2) ? (m0 + 128) : K;
    int tot = kmax / KC;

    int lrow = tid >> 2, lc8 = tid & 3;                // loader row 0..63, 16B chunk
    uint32_t adst = a_s + (lrow * LDP + lc8 * 8) * 2;
    uint32_t bdst = b_s + (lrow * LDP + lc8 * 8) * 2;

    float acc[4][8][4];
    #pragma unroll
    for (int i = 0; i < 4; i++)
        #pragma unroll
        for (int j = 0; j < 8; j++)
            #pragma unroll
            for (int q = 0; q < 4; q++) acc[i][j][q] = 0.f;

    auto load = [&](int c) {
        int k0 = c * KC;
        const __half* sa = A + (size_t)(m0 + lrow) * K + k0 + lc8 * 8;
        const __half* sb = B + (size_t)(n0 + lrow) * K + k0 + lc8 * 8;
        uint32_t ao = (c & 1) ? (uint32_t)SA_BYTES : 0u;
        uint32_t bo = (c & 1) ? (uint32_t)SB_BYTES : 0u;
        cp16(adst + ao, sa);
        cp16(adst + ao + 64 * LDP * 2, sa + (size_t)64 * K);
        cp16(bdst + bo, sb);
        cp16(bdst + bo + 64 * LDP * 2,  sb + (size_t)64 * K);
        cp16(bdst + bo + 128 * LDP * 2, sb + (size_t)128 * K);
        cp16(bdst + bo + 192 * LDP * 2, sb + (size_t)192 * K);
        CP_COMMIT();
    };

    load(0);
    for (int c = 0; c < tot; c++) {
        if (c + 1 < tot) { load(c + 1); CP_WAIT1(); }
        else             { CP_WAIT0(); }
        __syncthreads();

        uint32_t ab = a_s + (c & 1) * SA_BYTES;
        uint32_t bb = b_s + (c & 1) * SB_BYTES;
        #pragma unroll
        for (int kk = 0; kk < 2; kk++) {
            uint32_t afr[4][4], bfr[4][4];
            // A frags: [m0-7@k0, m8-15@k0, m0-7@k8, m8-15@k8]
            int ar = (lane & 7) + ((lane >> 3) & 1) * 8;
            int ak = kk * 16 + (lane >> 4) * 8;
            #pragma unroll
            for (int mi = 0; mi < 4; mi++)
                ldm_x4(afr[mi], ab + ((wm * 64 + mi * 16 + ar) * LDP + ak) * 2);
            // B frags merged x4: [n@k0, n@k8, n+8@k0, n+8@k8]
            int brow = (lane & 7) + ((lane >> 4) & 1) * 8;
            int bcol = kk * 16 + ((lane >> 3) & 1) * 8;
            #pragma unroll
            for (int p = 0; p < 4; p++)
                ldm_x4(bfr[p], bb + ((wn * 64 + p * 16 + brow) * LDP + bcol) * 2);
            #pragma unroll
            for (int mi = 0; mi < 4; mi++)
                #pragma unroll
                for (int ni = 0; ni < 8; ni++)
                    mma16816h(acc[mi][ni], afr[mi], &bfr[ni >> 1][(ni & 1) * 2]);
        }
        __syncthreads();
    }

    // epilogue
    int gr = lane >> 2, qc = (lane & 3) * 2;
    #pragma unroll
    for (int mi = 0; mi < 4; mi++) {
        #pragma unroll
        for (int half_ = 0; half_ < 2; half_++) {
            int m = m0 + wm * 64 + mi * 16 + gr + half_ * 8;
            int t = m & (TSEQ - 1);
            #pragma unroll
            for (int ni = 0; ni < 8; ni++) {
                int n = n0 + wn * 64 + ni * 8 + qc;
                float v0 = acc[mi][ni][half_ * 2 + 0] * scale;
                float v1 = acc[mi][ni][half_ * 2 + 1] * scale;
                if (bias) { v0 += bias[n]; v1 += bias[n + 1]; }
                if (ROPE) {
                    float2 sc = cs[(size_t)t * (CDIM / 2) + (n >> 1)];
                    float a = v0, b = v1;
                    v0 = a * sc.x - b * sc.y;
                    v1 = b * sc.x + a * sc.y;
                }
                if (OUT16) {
                    *(uint32_t*)&Ch[(size_t)m * N + n] = pack_h2(v0, v1);
                } else {
                    *(float2*)&Cf[(size_t)m * N + n] = make_float2(v0, v1);
                }
            }
        }
    }
}

// ---------------------------------------------------------------------------
// fused pre-pass: convert x + 4 weights to fp16, build RoPE table.
// work items: [0, 2M) x-float4 | [2M, 3M) weight-float4 | [3M, 4M) rope entries
// ---------------------------------------------------------------------------
#define XW4   (MTOT*CDIM/4)            // 2M
#define WW4   (CDIM*CDIM/4)            // 256K
__global__ void __launch_bounds__(256) prepass_k(
    const float4* __restrict__ x,
    const float4* __restrict__ Wq, const float4* __restrict__ Wk,
    const float4* __restrict__ Wv, const float4* __restrict__ Wf,
    __half* __restrict__ X16,
    __half* __restrict__ Wq16, __half* __restrict__ Wk16,
    __half* __restrict__ Wv16, __half* __restrict__ Wf16,
    float2* __restrict__ cs)
{
    int idx = blockIdx.x * 256 + threadIdx.x;
    if (idx < XW4 + 4 * WW4) {
        const float4* src;
        __half* dst;
        int off;
        if (idx < XW4) { src = x; dst = X16; off = idx; }
        else {
            int sub = idx - XW4;
            int w = sub / WW4;
            off = sub - w * WW4;
            src = (w == 0) ? Wq : (w == 1) ? Wk : (w == 2) ? Wv : Wf;
            dst = (w == 0) ? Wq16 : (w == 1) ? Wk16 : (w == 2) ? Wv16 : Wf16;
        }
        float4 v = src[off];
        *(uint2*)&dst[(size_t)off * 4] = make_uint2(pack_h2(v.x, v.y), pack_h2(v.z, v.w));
    } else {
        int r = idx - (XW4 + 4 * WW4);      // 0 .. 1M-1
        int t = r >> 9;                      // / (CDIM/2)
        int p = r & 511;
        float freq = powf(10000.0f, -(float)(2 * p) / (float)CDIM);
        float ang = (float)t * freq;
        float s, c;
        sincosf(ang, &s, &c);
        cs[r] = make_float2(c, s);
    }
}
#define PRE_ITEMS (XW4 + 4*WW4 + TSEQ*(CDIM/2))

// transpose V: [B,T,C] fp32 -> [B,C,T] fp16
__global__ void __launch_bounds__(256) tcvt_v_k(
    const float* __restrict__ V, __half* __restrict__ Vt)
{
    __shared__ float tile[32][33];
    int t0 = blockIdx.x * 32, c0 = blockIdx.y * 32, z = blockIdx.z;
    int tx = threadIdx.x, ty = threadIdx.y;   // 32 x 8
    const float* Vz = V + (size_t)z * TSEQ * CDIM;
    #pragma unroll
    for (int i = 0; i < 4; i++)
        tile[ty + 8 * i][tx] = Vz[(size_t)(t0 + ty + 8 * i) * CDIM + c0 + tx];
    __syncthreads();
    size_t ob = (size_t)z * CDIM * TSEQ;
    #pragma unroll
    for (int i = 0; i < 4; i++)
        Vt[ob + (size_t)(c0 + ty + 8 * i) * TSEQ + t0 + tx] =
            __float2half_rn(tile[tx][ty + 8 * i]);
}

// causal softmax: fp32 scores (prefix only) -> fp16 probs, zero-padded to the
// row's 128-block boundary.
__global__ void __launch_bounds__(256) softmax_h_k(
    const float* __restrict__ S, __half* __restrict__ P)
{
    long row = blockIdx.x;
    long b = row >> 11;
    int  t = (int)(row & (TSEQ - 1));
    const float* p = S + (b << 22) + ((long)t << 11);
    __half* ph = P + (b << 22) + ((long)t << 11);
    int n = t + 1;
    int kend = ((t >> 7) + 1) << 7;
    int tid = threadIdx.x;

    float4 v[2];
    float mx = -INFINITY;
    #pragma unroll
    for (int i = 0; i < 2; i++) {
        int base = (tid + 256 * i) * 4;
        if (base < n) {
            v[i] = *(const float4*)(p + base);
            float* f = (float*)&v[i];
            #pragma unroll
            for (int c = 0; c < 4; c++) {
                if (base + c >= n) f[c] = -INFINITY;
                mx = fmaxf(mx, f[c]);
            }
        } else {
            v[i] = make_float4(-INFINITY, -INFINITY, -INFINITY, -INFINITY);
        }
    }
    __shared__ float red[8];
    #pragma unroll
    for (int o = 16; o; o >>= 1) mx = fmaxf(mx, __shfl_xor_sync(~0u, mx, o));
    if ((tid & 31) == 0) red[tid >> 5] = mx;
    __syncthreads();
    mx = red[0];
    #pragma unroll
    for (int k = 1; k < 8; k++) mx = fmaxf(mx, red[k]);
    __syncthreads();

    float sum = 0.f;
    #pragma unroll
    for (int i = 0; i < 2; i++) {
        float* f = (float*)&v[i];
        #pragma unroll
        for (int c = 0; c < 4; c++) {
            float e = expf(f[c] - mx);
            f[c] = e;
            sum += e;
        }
    }
    #pragma unroll
    for (int o = 16; o; o >>= 1) sum += __shfl_xor_sync(~0u, sum, o);
    if ((tid & 31) == 0) red[tid >> 5] = sum;
    __syncthreads();
    sum = 0.f;
    #pragma unroll
    for (int k = 0; k < 8; k++) sum += red[k];
    float inv = 1.0f / sum;

    #pragma unroll
    for (int i = 0; i < 2; i++) {
        int base = (tid + 256 * i) * 4;
        if (base < kend) {
            float* f = (float*)&v[i];
            *(uint2*)(ph + base) =
                make_uint2(pack_h2(f[0] * inv, f[1] * inv),
                           pack_h2(f[2] * inv, f[3] * inv));
        }
    }
}

// ---------------------------------------------------------------------------
extern "C" void kernel_launch(void* const* d_in, const int* in_sizes, int n_in,
                              void* d_out, int out_size)
{
    const float* x  = (const float*)d_in[0];
    const float* Wq = (const float*)d_in[1];
    const float* bq = (const float*)d_in[2];
    const float* Wk = (const float*)d_in[3];
    const float* bk = (const float*)d_in[4];
    const float* Wv = (const float*)d_in[5];
    const float* bv = (const float*)d_in[6];
    const float* Wf = (const float*)d_in[7];
    const float* bf = (const float*)d_in[8];
    float* out = (float*)d_out;

    __half *X16,*Wq16,*Wk16,*Wv16,*Wf16,*Q16,*K16,*Vt,*P,*O16;
    float *V,*S;
    float2* CS;
    cudaGetSymbolAddress((void**)&X16,  g_X16);
    cudaGetSymbolAddress((void**)&Wq16, g_Wq16);
    cudaGetSymbolAddress((void**)&Wk16, g_Wk16);
    cudaGetSymbolAddress((void**)&Wv16, g_Wv16);
    cudaGetSymbolAddress((void**)&Wf16, g_Wf16);
    cudaGetSymbolAddress((void**)&Q16,  g_Q16);
    cudaGetSymbolAddress((void**)&K16,  g_K16);
    cudaGetSymbolAddress((void**)&V,    g_V);
    cudaGetSymbolAddress((void**)&Vt,   g_Vt);
    cudaGetSymbolAddress((void**)&S,    g_S);
    cudaGetSymbolAddress((void**)&P,    g_P);
    cudaGetSymbolAddress((void**)&O16,  g_O16);
    cudaGetSymbolAddress((void**)&CS,   g_CS);

    cudaFuncSetAttribute(gemm_h<1,0,1>, cudaFuncAttributeMaxDynamicSharedMemorySize, SMEM_DYN);
    cudaFuncSetAttribute(gemm_h<0,0,0>, cudaFuncAttributeMaxDynamicSharedMemorySize, SMEM_DYN);
    cudaFuncSetAttribute(gemm_h<0,1,0>, cudaFuncAttributeMaxDynamicSharedMemorySize, SMEM_DYN);
    cudaFuncSetAttribute(gemm_h<0,2,1>, cudaFuncAttributeMaxDynamicSharedMemorySize, SMEM_DYN);

    dim3 blk(256);

    // launch 0: fused converts + rope table
    prepass_k<<<PRE_ITEMS / 256, blk>>>(
        (const float4*)x, (const float4*)Wq, (const float4*)Wk,
        (const float4*)Wv, (const float4*)Wf,
        X16, Wq16, Wk16, Wv16, Wf16, CS);

    dim3 gProj(CDIM / 256, MTOT / 128, 1);   // 4 x 64

    // launch 1: Q ; launch 2: K
    gemm_h<1,0,1><<<gProj, blk, SMEM_DYN>>>(X16, Wq16, bq, CS, nullptr, Q16,
                                            CDIM, CDIM, 0, 0, 0, 1.0f);
    gemm_h<1,0,1><<<gProj, blk, SMEM_DYN>>>(X16, Wk16, bk, CS, nullptr, K16,
                                            CDIM, CDIM, 0, 0, 0, 1.0f);

    // launch 3 (ncu target): S = Q K^T / 32, causal tile-skip
    dim3 gS(TSEQ / 256, TSEQ / 128, BSZ);    // 8 x 16 x 4
    gemm_h<0,1,0><<<gS, blk, SMEM_DYN>>>(Q16, K16, nullptr, nullptr, S, nullptr,
                                         TSEQ, CDIM,
                                         (long)TSEQ * CDIM, (long)TSEQ * CDIM,
                                         (long)TSEQ * TSEQ, 1.0f / 32.0f);

    // launch 4: V projection (fp32 out)
    gemm_h<0,0,0><<<gProj, blk, SMEM_DYN>>>(X16, Wv16, bv, nullptr, V, nullptr,
                                            CDIM, CDIM, 0, 0, 0, 1.0f);
    // launch 5: V transpose+convert
    dim3 gT(TSEQ / 32, CDIM / 32, BSZ);
    tcvt_v_k<<<gT, dim3(32, 8)>>>(V, Vt);

    // launch 6: softmax
    softmax_h_k<<<BSZ * TSEQ, blk>>>(S, P);

    // launch 7: O = P V (causal k-limit) -> fp16
    dim3 gPV(CDIM / 256, TSEQ / 128, BSZ);   // 4 x 16 x 4
    gemm_h<0,2,1><<<gPV, blk, SMEM_DYN>>>(P, Vt, nullptr, nullptr, nullptr, O16,
                                          CDIM, TSEQ,
                                          (long)TSEQ * TSEQ, (long)CDIM * TSEQ,
                                          (long)TSEQ * CDIM, 1.0f);

    // launch 8: out = O Wf^T + bf (fp32)
    gemm_h<0,0,0><<<gProj, blk, SMEM_DYN>>>(O16, Wf16, bf, nullptr, out, nullptr,
                                            CDIM, CDIM, 0, 0, 0, 1.0f);
}

// round 8
// speedup vs baseline: 1.0535x; 1.0535x over previous
#include <cuda_runtime.h>
#include <cuda_fp16.h>
#include <math.h>
#include <cstdint>

#define BSZ  4
#define TSEQ 2048
#define CDIM 1024
#define MTOT (BSZ*TSEQ)

#define KC 32
#define LDP 40                         // padded row length (halfs)
#define TILE_BYTES (128*LDP*2)         // 10240 per matrix per buffer

// ------------------------- persistent scratch ------------------------------
__device__ __align__(16) __half g_X16[(size_t)MTOT*CDIM];
__device__ __align__(16) __half g_Wq16[(size_t)CDIM*CDIM];
__device__ __align__(16) __half g_Wk16[(size_t)CDIM*CDIM];
__device__ __align__(16) __half g_Wv16[(size_t)CDIM*CDIM];
__device__ __align__(16) __half g_Wf16[(size_t)CDIM*CDIM];
__device__ __align__(16) __half g_Q16[(size_t)MTOT*CDIM];
__device__ __align__(16) __half g_K16[(size_t)MTOT*CDIM];
__device__ __align__(16) float  g_V  [(size_t)MTOT*CDIM];
__device__ __align__(16) __half g_Vt [(size_t)BSZ*CDIM*TSEQ];
__device__ __align__(16) float  g_S  [(size_t)BSZ*TSEQ*TSEQ];
__device__ __align__(16) __half g_P  [(size_t)BSZ*TSEQ*TSEQ];
__device__ __align__(16) __half g_O16[(size_t)MTOT*CDIM];
__device__ __align__(16) float2 g_CS [(size_t)TSEQ*(CDIM/2)];

// ------------------------------ ptx helpers --------------------------------
__device__ __forceinline__ uint32_t smem_u32(const void* p) {
    uint32_t a;
    asm("{ .reg .u64 t; cvta.to.shared.u64 t, %1; cvt.u32.u64 %0, t; }"
        : "=r"(a) : "l"(p));
    return a;
}
__device__ __forceinline__ void cp16(uint32_t dst, const void* src) {
    asm volatile("cp.async.cg.shared.global [%0], [%1], 16;" :: "r"(dst), "l"(src));
}
#define CP_COMMIT() asm volatile("cp.async.commit_group;")
#define CP_WAIT0()  asm volatile("cp.async.wait_group 0;")
#define CP_WAIT1()  asm volatile("cp.async.wait_group 1;")

__device__ __forceinline__ void ldm_x4(uint32_t* r, uint32_t addr) {
    asm volatile("ldmatrix.sync.aligned.m8n8.x4.shared.b16 {%0,%1,%2,%3}, [%4];"
                 : "=r"(r[0]), "=r"(r[1]), "=r"(r[2]), "=r"(r[3]) : "r"(addr));
}
__device__ __forceinline__ void mma16816h(float* c, const uint32_t* a, const uint32_t* b) {
    asm volatile("mma.sync.aligned.m16n8k16.row.col.f32.f16.f16.f32 "
                 "{%0,%1,%2,%3}, {%4,%5,%6,%7}, {%8,%9}, {%0,%1,%2,%3};"
                 : "+f"(c[0]), "+f"(c[1]), "+f"(c[2]), "+f"(c[3])
                 : "r"(a[0]), "r"(a[1]), "r"(a[2]), "r"(a[3]), "r"(b[0]), "r"(b[1]));
}
__device__ __forceinline__ uint32_t pack_h2(float x, float y) {
    __half2 h = __floats2half2_rn(x, y);
    return *(uint32_t*)&h;
}

// ---------------------------------------------------------------------------
// fp16 NT GEMM, 128x128 CTA tile, 128 threads = 4 warps (2x2) of 64x64 tiles.
// 2 CTAs/SM. C[m,n] = scale*sum_k A[m,k]*B[n,k] (+bias, +RoPE). fp32 accum.
// CMODE: 0 none, 1 causal tile-skip, 2 causal k-limit.
// OUT16: 1 -> fp16 out, 0 -> fp32 out.
// ---------------------------------------------------------------------------
template<int ROPE, int CMODE, int OUT16>
__global__ void __launch_bounds__(128, 2) gemm_h(
    const __half* __restrict__ A, const __half* __restrict__ B,
    const float* __restrict__ bias, const float2* __restrict__ cs,
    float* __restrict__ Cf, __half* __restrict__ Ch,
    int N, int K, long sA, long sB, long sC, float scale)
{
    int m0 = blockIdx.y * 128, n0 = blockIdx.x * 128;
    if (CMODE == 1 && n0 > m0 + 127) return;
    long z = blockIdx.z;
    A += z * sA; B += z * sB;
    if (OUT16) Ch += z * sC; else Cf += z * sC;

    __shared__ __align__(16) __half As[2][128 * LDP];
    __shared__ __align__(16) __half Bs[2][128 * LDP];

    int tid = threadIdx.x, lane = tid & 31, wid = tid >> 5;
    int wm = wid & 1, wn = wid >> 1;           // warp tile (wm*64, wn*64)

    int kmax = (CMODE == 2) ? (m0 + 128) : K;
    int tot = kmax / KC;

    int lrow = tid >> 2, lc8 = tid & 3;        // loader row 0..31 (+32*i), chunk
    uint32_t a_s = smem_u32(As), b_s = smem_u32(Bs);
    uint32_t adst = a_s + (lrow * LDP + lc8 * 8) * 2;
    uint32_t bdst = b_s + (lrow * LDP + lc8 * 8) * 2;

    float acc[4][8][4];
    #pragma unroll
    for (int i = 0; i < 4; i++)
        #pragma unroll
        for (int j = 0; j < 8; j++)
            #pragma unroll
            for (int q = 0; q < 4; q++) acc[i][j][q] = 0.f;

    auto load = [&](int c) {
        int k0 = c * KC;
        const __half* sa = A + (size_t)(m0 + lrow) * K + k0 + lc8 * 8;
        const __half* sb = B + (size_t)(n0 + lrow) * K + k0 + lc8 * 8;
        uint32_t off = (c & 1) ? (uint32_t)TILE_BYTES : 0u;
        #pragma unroll
        for (int i = 0; i < 4; i++) {
            cp16(adst + off + i * 32 * LDP * 2, sa + (size_t)(32 * i) * K);
            cp16(bdst + off + i * 32 * LDP * 2, sb + (size_t)(32 * i) * K);
        }
        CP_COMMIT();
    };

    load(0);
    for (int c = 0; c < tot; c++) {
        if (c + 1 < tot) { load(c + 1); CP_WAIT1(); }
        else             { CP_WAIT0(); }
        __syncthreads();

        uint32_t ab = a_s + (c & 1) * TILE_BYTES;
        uint32_t bb = b_s + (c & 1) * TILE_BYTES;
        #pragma unroll
        for (int kk = 0; kk < 2; kk++) {
            uint32_t afr[4][4], bfr[4][4];
            // A frags
            int ar = (lane & 7) + ((lane >> 3) & 1) * 8;
            int ak = kk * 16 + (lane >> 4) * 8;
            #pragma unroll
            for (int mi = 0; mi < 4; mi++)
                ldm_x4(afr[mi], ab + ((wm * 64 + mi * 16 + ar) * LDP + ak) * 2);
            // B frags merged x4: [n@k0, n@k8, n+8@k0, n+8@k8]
            int brow = (lane & 7) + ((lane >> 4) & 1) * 8;
            int bcol = kk * 16 + ((lane >> 3) & 1) * 8;
            #pragma unroll
            for (int p = 0; p < 4; p++)
                ldm_x4(bfr[p], bb + ((wn * 64 + p * 16 + brow) * LDP + bcol) * 2);
            #pragma unroll
            for (int mi = 0; mi < 4; mi++)
                #pragma unroll
                for (int ni = 0; ni < 8; ni++)
                    mma16816h(acc[mi][ni], afr[mi], &bfr[ni >> 1][(ni & 1) * 2]);
        }
        __syncthreads();
    }

    // epilogue
    int gr = lane >> 2, qc = (lane & 3) * 2;
    #pragma unroll
    for (int mi = 0; mi < 4; mi++) {
        #pragma unroll
        for (int half_ = 0; half_ < 2; half_++) {
            int m = m0 + wm * 64 + mi * 16 + gr + half_ * 8;
            int t = m & (TSEQ - 1);
            #pragma unroll
            for (int ni = 0; ni < 8; ni++) {
                int n = n0 + wn * 64 + ni * 8 + qc;
                float v0 = acc[mi][ni][half_ * 2 + 0] * scale;
                float v1 = acc[mi][ni][half_ * 2 + 1] * scale;
                if (bias) { v0 += bias[n]; v1 += bias[n + 1]; }
                if (ROPE) {
                    float2 sc = cs[(size_t)t * (CDIM / 2) + (n >> 1)];
                    float a = v0, b = v1;
                    v0 = a * sc.x - b * sc.y;
                    v1 = b * sc.x + a * sc.y;
                }
                if (OUT16) {
                    *(uint32_t*)&Ch[(size_t)m * N + n] = pack_h2(v0, v1);
                } else {
                    *(float2*)&Cf[(size_t)m * N + n] = make_float2(v0, v1);
                }
            }
        }
    }
}

// ---------------------------------------------------------------------------
// fused pre-pass: convert x + 4 weights to fp16, build RoPE table.
// ---------------------------------------------------------------------------
#define XW4   (MTOT*CDIM/4)            // 2M
#define WW4   (CDIM*CDIM/4)            // 256K
__global__ void __launch_bounds__(256) prepass_k(
    const float4* __restrict__ x,
    const float4* __restrict__ Wq, const float4* __restrict__ Wk,
    const float4* __restrict__ Wv, const float4* __restrict__ Wf,
    __half* __restrict__ X16,
    __half* __restrict__ Wq16, __half* __restrict__ Wk16,
    __half* __restrict__ Wv16, __half* __restrict__ Wf16,
    float2* __restrict__ cs)
{
    int idx = blockIdx.x * 256 + threadIdx.x;
    if (idx < XW4 + 4 * WW4) {
        const float4* src;
        __half* dst;
        int off;
        if (idx < XW4) { src = x; dst = X16; off = idx; }
        else {
            int sub = idx - XW4;
            int w = sub / WW4;
            off = sub - w * WW4;
            src = (w == 0) ? Wq : (w == 1) ? Wk : (w == 2) ? Wv : Wf;
            dst = (w == 0) ? Wq16 : (w == 1) ? Wk16 : (w == 2) ? Wv16 : Wf16;
        }
        float4 v = src[off];
        *(uint2*)&dst[(size_t)off * 4] = make_uint2(pack_h2(v.x, v.y), pack_h2(v.z, v.w));
    } else {
        int r = idx - (XW4 + 4 * WW4);       // 0 .. 1M-1
        int t = r >> 9;
        int p = r & 511;
        float freq = powf(10000.0f, -(float)(2 * p) / (float)CDIM);
        float ang = (float)t * freq;
        float s, c;
        sincosf(ang, &s, &c);
        cs[r] = make_float2(c, s);
    }
}
#define PRE_ITEMS (XW4 + 4*WW4 + TSEQ*(CDIM/2))

// transpose V: [B,T,C] fp32 -> [B,C,T] fp16
__global__ void __launch_bounds__(256) tcvt_v_k(
    const float* __restrict__ V, __half* __restrict__ Vt)
{
    __shared__ float tile[32][33];
    int t0 = blockIdx.x * 32, c0 = blockIdx.y * 32, z = blockIdx.z;
    int tx = threadIdx.x, ty = threadIdx.y;   // 32 x 8
    const float* Vz = V + (size_t)z * TSEQ * CDIM;
    #pragma unroll
    for (int i = 0; i < 4; i++)
        tile[ty + 8 * i][tx] = Vz[(size_t)(t0 + ty + 8 * i) * CDIM + c0 + tx];
    __syncthreads();
    size_t ob = (size_t)z * CDIM * TSEQ;
    #pragma unroll
    for (int i = 0; i < 4; i++)
        Vt[ob + (size_t)(c0 + ty + 8 * i) * TSEQ + t0 + tx] =
            __float2half_rn(tile[tx][ty + 8 * i]);
}

// causal softmax: fp32 scores (prefix only) -> fp16 probs, zero-padded to the
// row's 128-block boundary.
__global__ void __launch_bounds__(256) softmax_h_k(
    const float* __restrict__ S, __half* __restrict__ P)
{
    long row = blockIdx.x;
    long b = row >> 11;
    int  t = (int)(row & (TSEQ - 1));
    const float* p = S + (b << 22) + ((long)t << 11);
    __half* ph = P + (b << 22) + ((long)t << 11);
    int n = t + 1;
    int kend = ((t >> 7) + 1) << 7;
    int tid = threadIdx.x;

    float4 v[2];
    float mx = -INFINITY;
    #pragma unroll
    for (int i = 0; i < 2; i++) {
        int base = (tid + 256 * i) * 4;
        if (base < n) {
            v[i] = *(const float4*)(p + base);
            float* f = (float*)&v[i];
            #pragma unroll
            for (int c = 0; c < 4; c++) {
                if (base + c >= n) f[c] = -INFINITY;
                mx = fmaxf(mx, f[c]);
            }
        } else {
            v[i] = make_float4(-INFINITY, -INFINITY, -INFINITY, -INFINITY);
        }
    }
    __shared__ float red[8];
    #pragma unroll
    for (int o = 16; o; o >>= 1) mx = fmaxf(mx, __shfl_xor_sync(~0u, mx, o));
    if ((tid & 31) == 0) red[tid >> 5] = mx;
    __syncthreads();
    mx = red[0];
    #pragma unroll
    for (int k = 1; k < 8; k++) mx = fmaxf(mx, red[k]);
    __syncthreads();

    float sum = 0.f;
    #pragma unroll
    for (int i = 0; i < 2; i++) {
        float* f = (float*)&v[i];
        #pragma unroll
        for (int c = 0; c < 4; c++) {
            float e = expf(f[c] - mx);
            f[c] = e;
            sum += e;
        }
    }
    #pragma unroll
    for (int o = 16; o; o >>= 1) sum += __shfl_xor_sync(~0u, sum, o);
    if ((tid & 31) == 0) red[tid >> 5] = sum;
    __syncthreads();
    sum = 0.f;
    #pragma unroll
    for (int k = 0; k < 8; k++) sum += red[k];
    float inv = 1.0f / sum;

    #pragma unroll
    for (int i = 0; i < 2; i++) {
        int base = (tid + 256 * i) * 4;
        if (base < kend) {
            float* f = (float*)&v[i];
            *(uint2*)(ph + base) =
                make_uint2(pack_h2(f[0] * inv, f[1] * inv),
                           pack_h2(f[2] * inv, f[3] * inv));
        }
    }
}

// ---------------------------------------------------------------------------
extern "C" void kernel_launch(void* const* d_in, const int* in_sizes, int n_in,
                              void* d_out, int out_size)
{
    const float* x  = (const float*)d_in[0];
    const float* Wq = (const float*)d_in[1];
    const float* bq = (const float*)d_in[2];
    const float* Wk = (const float*)d_in[3];
    const float* bk = (const float*)d_in[4];
    const float* Wv = (const float*)d_in[5];
    const float* bv = (const float*)d_in[6];
    const float* Wf = (const float*)d_in[7];
    const float* bf = (const float*)d_in[8];
    float* out = (float*)d_out;

    __half *X16,*Wq16,*Wk16,*Wv16,*Wf16,*Q16,*K16,*Vt,*P,*O16;
    float *V,*S;
    float2* CS;
    cudaGetSymbolAddress((void**)&X16,  g_X16);
    cudaGetSymbolAddress((void**)&Wq16, g_Wq16);
    cudaGetSymbolAddress((void**)&Wk16, g_Wk16);
    cudaGetSymbolAddress((void**)&Wv16, g_Wv16);
    cudaGetSymbolAddress((void**)&Wf16, g_Wf16);
    cudaGetSymbolAddress((void**)&Q16,  g_Q16);
    cudaGetSymbolAddress((void**)&K16,  g_K16);
    cudaGetSymbolAddress((void**)&V,    g_V);
    cudaGetSymbolAddress((void**)&Vt,   g_Vt);
    cudaGetSymbolAddress((void**)&S,    g_S);
    cudaGetSymbolAddress((void**)&P,    g_P);
    cudaGetSymbolAddress((void**)&O16,  g_O16);
    cudaGetSymbolAddress((void**)&CS,   g_CS);

    dim3 gblk(128);
    dim3 blk(256);

    // launch 0: fused converts + rope table
    prepass_k<<<PRE_ITEMS / 256, blk>>>(
        (const float4*)x, (const float4*)Wq, (const float4*)Wk,
        (const float4*)Wv, (const float4*)Wf,
        X16, Wq16, Wk16, Wv16, Wf16, CS);

    dim3 gProj(CDIM / 128, MTOT / 128, 1);   // 8 x 64

    // launch 1: Q ; launch 2: K
    gemm_h<1,0,1><<<gProj, gblk>>>(X16, Wq16, bq, CS, nullptr, Q16,
                                   CDIM, CDIM, 0, 0, 0, 1.0f);
    gemm_h<1,0,1><<<gProj, gblk>>>(X16, Wk16, bk, CS, nullptr, K16,
                                   CDIM, CDIM, 0, 0, 0, 1.0f);

    // launch 3 (ncu target): S = Q K^T / 32, causal tile-skip
    dim3 gS(TSEQ / 128, TSEQ / 128, BSZ);    // 16 x 16 x 4
    gemm_h<0,1,0><<<gS, gblk>>>(Q16, K16, nullptr, nullptr, S, nullptr,
                                TSEQ, CDIM,
                                (long)TSEQ * CDIM, (long)TSEQ * CDIM,
                                (long)TSEQ * TSEQ, 1.0f / 32.0f);

    // launch 4: V projection (fp32 out)
    gemm_h<0,0,0><<<gProj, gblk>>>(X16, Wv16, bv, nullptr, V, nullptr,
                                   CDIM, CDIM, 0, 0, 0, 1.0f);
    // launch 5: V transpose+convert
    dim3 gT(TSEQ / 32, CDIM / 32, BSZ);
    tcvt_v_k<<<gT, dim3(32, 8)>>>(V, Vt);

    // launch 6: softmax
    softmax_h_k<<<BSZ * TSEQ, blk>>>(S, P);

    // launch 7: O = P V (causal k-limit) -> fp16
    dim3 gPV(CDIM / 128, TSEQ / 128, BSZ);   // 8 x 16 x 4
    gemm_h<0,2,1><<<gPV, gblk>>>(P, Vt, nullptr, nullptr, nullptr, O16,
                                 CDIM, TSEQ,
                                 (long)TSEQ * TSEQ, (long)CDIM * TSEQ,
                                 (long)TSEQ * CDIM, 1.0f);

    // launch 8: out = O Wf^T + bf (fp32)
    gemm_h<0,0,0><<<gProj, gblk>>>(O16, Wf16, bf, nullptr, out, nullptr,
                                   CDIM, CDIM, 0, 0, 0, 1.0f);
}

// round 10
// speedup vs baseline: 1.1829x; 1.1228x over previous
#include <cuda_runtime.h>
#include <cuda_fp16.h>
#include <math.h>
#include <cstdint>

#define BSZ  4
#define TSEQ 2048
#define CDIM 1024
#define MTOT (BSZ*TSEQ)

#define KC 32
#define LDP 40                         // padded row length (halfs)
#define TILE_BYTES (128*LDP*2)         // 10240 per matrix per stage
#define NSTAGE 3
#define SMEM_DYN (2*NSTAGE*TILE_BYTES) // 61440

// ------------------------- persistent scratch ------------------------------
__device__ __align__(16) __half g_X16[(size_t)MTOT*CDIM];
__device__ __align__(16) __half g_Wq16[(size_t)CDIM*CDIM];
__device__ __align__(16) __half g_Wk16[(size_t)CDIM*CDIM];
__device__ __align__(16) __half g_Wv16[(size_t)CDIM*CDIM];
__device__ __align__(16) __half g_Wf16[(size_t)CDIM*CDIM];
__device__ __align__(16) __half g_Q16[(size_t)MTOT*CDIM];
__device__ __align__(16) __half g_K16[(size_t)MTOT*CDIM];
__device__ __align__(16) float  g_V  [(size_t)MTOT*CDIM];
__device__ __align__(16) __half g_Vt [(size_t)BSZ*CDIM*TSEQ];
__device__ __align__(16) float  g_S  [(size_t)BSZ*TSEQ*TSEQ];
__device__ __align__(16) __half g_P  [(size_t)BSZ*TSEQ*TSEQ];
__device__ __align__(16) __half g_O16[(size_t)MTOT*CDIM];
__device__ __align__(16) float2 g_CS [(size_t)TSEQ*(CDIM/2)];

// ------------------------------ ptx helpers --------------------------------
__device__ __forceinline__ uint32_t smem_u32(const void* p) {
    uint32_t a;
    asm("{ .reg .u64 t; cvta.to.shared.u64 t, %1; cvt.u32.u64 %0, t; }"
        : "=r"(a) : "l"(p));
    return a;
}
__device__ __forceinline__ void cp16(uint32_t dst, const void* src) {
    asm volatile("cp.async.cg.shared.global [%0], [%1], 16;" :: "r"(dst), "l"(src));
}
#define CP_COMMIT() asm volatile("cp.async.commit_group;")
#define CP_WAIT0()  asm volatile("cp.async.wait_group 0;")
#define CP_WAIT1()  asm volatile("cp.async.wait_group 1;")

__device__ __forceinline__ void ldm_x4(uint32_t* r, uint32_t addr) {
    asm volatile("ldmatrix.sync.aligned.m8n8.x4.shared.b16 {%0,%1,%2,%3}, [%4];"
                 : "=r"(r[0]), "=r"(r[1]), "=r"(r[2]), "=r"(r[3]) : "r"(addr));
}
__device__ __forceinline__ void mma16816h(float* c, const uint32_t* a, const uint32_t* b) {
    asm volatile("mma.sync.aligned.m16n8k16.row.col.f32.f16.f16.f32 "
                 "{%0,%1,%2,%3}, {%4,%5,%6,%7}, {%8,%9}, {%0,%1,%2,%3};"
                 : "+f"(c[0]), "+f"(c[1]), "+f"(c[2]), "+f"(c[3])
                 : "r"(a[0]), "r"(a[1]), "r"(a[2]), "r"(a[3]), "r"(b[0]), "r"(b[1]));
}
__device__ __forceinline__ uint32_t pack_h2(float x, float y) {
    __half2 h = __floats2half2_rn(x, y);
    return *(uint32_t*)&h;
}

// ---------------------------------------------------------------------------
// fp16 NT GEMM, 128x128 CTA tile, 128 threads = 4 warps (2x2) of 64x64 tiles.
// 3-stage cp.async ring, ONE __syncthreads per KC chunk. 2 CTAs/SM.
// C[m,n] = scale*sum_k A[m,k]*B[n,k] (+bias, +RoPE). fp32 accumulate.
// CMODE: 0 none, 1 causal tile-skip, 2 causal k-limit.
// OUT16: 1 -> fp16 out, 0 -> fp32 out.
// ---------------------------------------------------------------------------
template<int ROPE, int CMODE, int OUT16>
__global__ void __launch_bounds__(128, 2) gemm_h(
    const __half* __restrict__ A, const __half* __restrict__ B,
    const float* __restrict__ bias, const float2* __restrict__ cs,
    float* __restrict__ Cf, __half* __restrict__ Ch,
    int N, int K, long sA, long sB, long sC, float scale)
{
    int m0 = blockIdx.y * 128, n0 = blockIdx.x * 128;
    if (CMODE == 1 && n0 > m0 + 127) return;
    long z = blockIdx.z;
    A += z * sA; B += z * sB;
    if (OUT16) Ch += z * sC; else Cf += z * sC;

    extern __shared__ __align__(16) char smem_raw[];
    uint32_t a_s = smem_u32(smem_raw);                    // A stages: 3 x 10240
    uint32_t b_s = a_s + NSTAGE * TILE_BYTES;             // B stages: 3 x 10240

    int tid = threadIdx.x, lane = tid & 31, wid = tid >> 5;
    int wm = wid & 1, wn = wid >> 1;            // warp tile (wm*64, wn*64)

    int kmax = (CMODE == 2) ? (m0 + 128) : K;
    int tot = kmax / KC;

    int lrow = tid >> 2, lc8 = tid & 3;         // loader row 0..31 (+32*i), chunk
    uint32_t adst = a_s + (lrow * LDP + lc8 * 8) * 2;
    uint32_t bdst = b_s + (lrow * LDP + lc8 * 8) * 2;

    float acc[4][8][4];
    #pragma unroll
    for (int i = 0; i < 4; i++)
        #pragma unroll
        for (int j = 0; j < 8; j++)
            #pragma unroll
            for (int q = 0; q < 4; q++) acc[i][j][q] = 0.f;

    auto load = [&](int c) {
        int k0 = c * KC;
        int st = c % NSTAGE;
        const __half* sa = A + (size_t)(m0 + lrow) * K + k0 + lc8 * 8;
        const __half* sb = B + (size_t)(n0 + lrow) * K + k0 + lc8 * 8;
        uint32_t off = (uint32_t)(st * TILE_BYTES);
        #pragma unroll
        for (int i = 0; i < 4; i++) {
            cp16(adst + off + i * 32 * LDP * 2, sa + (size_t)(32 * i) * K);
            cp16(bdst + off + i * 32 * LDP * 2, sb + (size_t)(32 * i) * K);
        }
        CP_COMMIT();
    };

    load(0);
    if (tot > 1) load(1);

    for (int c = 0; c < tot; c++) {
        if (c + 1 < tot) CP_WAIT1(); else CP_WAIT0();
        __syncthreads();

        // prefetch stage c+2 into ring slot freed by compute(c-1)
        if (c + 2 < tot) load(c + 2);

        int st = c % NSTAGE;
        uint32_t ab = a_s + st * TILE_BYTES;
        uint32_t bb = b_s + st * TILE_BYTES;
        #pragma unroll
        for (int kk = 0; kk < 2; kk++) {
            uint32_t afr[4][4], bfr[4][4];
            int ar = (lane & 7) + ((lane >> 3) & 1) * 8;
            int ak = kk * 16 + (lane >> 4) * 8;
            #pragma unroll
            for (int mi = 0; mi < 4; mi++)
                ldm_x4(afr[mi], ab + ((wm * 64 + mi * 16 + ar) * LDP + ak) * 2);
            int brow = (lane & 7) + ((lane >> 4) & 1) * 8;
            int bcol = kk * 16 + ((lane >> 3) & 1) * 8;
            #pragma unroll
            for (int p = 0; p < 4; p++)
                ldm_x4(bfr[p], bb + ((wn * 64 + p * 16 + brow) * LDP + bcol) * 2);
            #pragma unroll
            for (int mi = 0; mi < 4; mi++)
                #pragma unroll
                for (int ni = 0; ni < 8; ni++)
                    mma16816h(acc[mi][ni], afr[mi], &bfr[ni >> 1][(ni & 1) * 2]);
        }
    }

    // epilogue
    int gr = lane >> 2, qc = (lane & 3) * 2;
    #pragma unroll
    for (int mi = 0; mi < 4; mi++) {
        #pragma unroll
        for (int half_ = 0; half_ < 2; half_++) {
            int m = m0 + wm * 64 + mi * 16 + gr + half_ * 8;
            int t = m & (TSEQ - 1);
            #pragma unroll
            for (int ni = 0; ni < 8; ni++) {
                int n = n0 + wn * 64 + ni * 8 + qc;
                float v0 = acc[mi][ni][half_ * 2 + 0] * scale;
                float v1 = acc[mi][ni][half_ * 2 + 1] * scale;
                if (bias) { v0 += bias[n]; v1 += bias[n + 1]; }
                if (ROPE) {
                    float2 sc = cs[(size_t)t * (CDIM / 2) + (n >> 1)];
                    float a = v0, b = v1;
                    v0 = a * sc.x - b * sc.y;
                    v1 = b * sc.x + a * sc.y;
                }
                if (OUT16) {
                    *(uint32_t*)&Ch[(size_t)m * N + n] = pack_h2(v0, v1);
                } else {
                    *(float2*)&Cf[(size_t)m * N + n] = make_float2(v0, v1);
                }
            }
        }
    }
}

// ---------------------------------------------------------------------------
// fused pre-pass: convert x + 4 weights to fp16, build RoPE table.
// ---------------------------------------------------------------------------
#define XW4   (MTOT*CDIM/4)            // 2M
#define WW4   (CDIM*CDIM/4)            // 256K
__global__ void __launch_bounds__(256) prepass_k(
    const float4* __restrict__ x,
    const float4* __restrict__ Wq, const float4* __restrict__ Wk,
    const float4* __restrict__ Wv, const float4* __restrict__ Wf,
    __half* __restrict__ X16,
    __half* __restrict__ Wq16, __half* __restrict__ Wk16,
    __half* __restrict__ Wv16, __half* __restrict__ Wf16,
    float2* __restrict__ cs)
{
    int idx = blockIdx.x * 256 + threadIdx.x;
    if (idx < XW4 + 4 * WW4) {
        const float4* src;
        __half* dst;
        int off;
        if (idx < XW4) { src = x; dst = X16; off = idx; }
        else {
            int sub = idx - XW4;
            int w = sub / WW4;
            off = sub - w * WW4;
            src = (w == 0) ? Wq : (w == 1) ? Wk : (w == 2) ? Wv : Wf;
            dst = (w == 0) ? Wq16 : (w == 1) ? Wk16 : (w == 2) ? Wv16 : Wf16;
        }
        float4 v = src[off];
        *(uint2*)&dst[(size_t)off * 4] = make_uint2(pack_h2(v.x, v.y), pack_h2(v.z, v.w));
    } else {
        int r = idx - (XW4 + 4 * WW4);       // 0 .. 1M-1
        int t = r >> 9;
        int p = r & 511;
        float freq = powf(10000.0f, -(float)(2 * p) / (float)CDIM);
        float ang = (float)t * freq;
        float s, c;
        sincosf(ang, &s, &c);
        cs[r] = make_float2(c, s);
    }
}
#define PRE_ITEMS (XW4 + 4*WW4 + TSEQ*(CDIM/2))

// transpose V: [B,T,C] fp32 -> [B,C,T] fp16
__global__ void __launch_bounds__(256) tcvt_v_k(
    const float* __restrict__ V, __half* __restrict__ Vt)
{
    __shared__ float tile[32][33];
    int t0 = blockIdx.x * 32, c0 = blockIdx.y * 32, z = blockIdx.z;
    int tx = threadIdx.x, ty = threadIdx.y;   // 32 x 8
    const float* Vz = V + (size_t)z * TSEQ * CDIM;
    #pragma unroll
    for (int i = 0; i < 4; i++)
        tile[ty + 8 * i][tx] = Vz[(size_t)(t0 + ty + 8 * i) * CDIM + c0 + tx];
    __syncthreads();
    size_t ob = (size_t)z * CDIM * TSEQ;
    #pragma unroll
    for (int i = 0; i < 4; i++)
        Vt[ob + (size_t)(c0 + ty + 8 * i) * TSEQ + t0 + tx] =
            __float2half_rn(tile[tx][ty + 8 * i]);
}

// causal softmax: fp32 scores (prefix only) -> fp16 probs, zero-padded to the
// row's 128-block boundary.
__global__ void __launch_bounds__(256) softmax_h_k(
    const float* __restrict__ S, __half* __restrict__ P)
{
    long row = blockIdx.x;
    long b = row >> 11;
    int  t = (int)(row & (TSEQ - 1));
    const float* p = S + (b << 22) + ((long)t << 11);
    __half* ph = P + (b << 22) + ((long)t << 11);
    int n = t + 1;
    int kend = ((t >> 7) + 1) << 7;
    int tid = threadIdx.x;

    float4 v[2];
    float mx = -INFINITY;
    #pragma unroll
    for (int i = 0; i < 2; i++) {
        int base = (tid + 256 * i) * 4;
        if (base < n) {
            v[i] = *(const float4*)(p + base);
            float* f = (float*)&v[i];
            #pragma unroll
            for (int c = 0; c < 4; c++) {
                if (base + c >= n) f[c] = -INFINITY;
                mx = fmaxf(mx, f[c]);
            }
        } else {
            v[i] = make_float4(-INFINITY, -INFINITY, -INFINITY, -INFINITY);
        }
    }
    __shared__ float red[8];
    #pragma unroll
    for (int o = 16; o; o >>= 1) mx = fmaxf(mx, __shfl_xor_sync(~0u, mx, o));
    if ((tid & 31) == 0) red[tid >> 5] = mx;
    __syncthreads();
    mx = red[0];
    #pragma unroll
    for (int k = 1; k < 8; k++) mx = fmaxf(mx, red[k]);
    __syncthreads();

    float sum = 0.f;
    #pragma unroll
    for (int i = 0; i < 2; i++) {
        float* f = (float*)&v[i];
        #pragma unroll
        for (int c = 0; c < 4; c++) {
            float e = expf(f[c] - mx);
            f[c] = e;
            sum += e;
        }
    }
    #pragma unroll
    for (int o = 16; o; o >>= 1) sum += __shfl_xor_sync(~0u, sum, o);
    if ((tid & 31) == 0) red[tid >> 5] = sum;
    __syncthreads();
    sum = 0.f;
    #pragma unroll
    for (int k = 0; k < 8; k++) sum += red[k];
    float inv = 1.0f / sum;

    #pragma unroll
    for (int i = 0; i < 2; i++) {
        int base = (tid + 256 * i) * 4;
        if (base < kend) {
            float* f = (float*)&v[i];
            *(uint2*)(ph + base) =
                make_uint2(pack_h2(f[0] * inv, f[1] * inv),
                           pack_h2(f[2] * inv, f[3] * inv));
        }
    }
}

// ---------------------------------------------------------------------------
extern "C" void kernel_launch(void* const* d_in, const int* in_sizes, int n_in,
                              void* d_out, int out_size)
{
    const float* x  = (const float*)d_in[0];
    const float* Wq = (const float*)d_in[1];
    const float* bq = (const float*)d_in[2];
    const float* Wk = (const float*)d_in[3];
    const float* bk = (const float*)d_in[4];
    const float* Wv = (const float*)d_in[5];
    const float* bv = (const float*)d_in[6];
    const float* Wf = (const float*)d_in[7];
    const float* bf = (const float*)d_in[8];
    float* out = (float*)d_out;

    __half *X16,*Wq16,*Wk16,*Wv16,*Wf16,*Q16,*K16,*Vt,*P,*O16;
    float *V,*S;
    float2* CS;
    cudaGetSymbolAddress((void**)&X16,  g_X16);
    cudaGetSymbolAddress((void**)&Wq16, g_Wq16);
    cudaGetSymbolAddress((void**)&Wk16, g_Wk16);
    cudaGetSymbolAddress((void**)&Wv16, g_Wv16);
    cudaGetSymbolAddress((void**)&Wf16, g_Wf16);
    cudaGetSymbolAddress((void**)&Q16,  g_Q16);
    cudaGetSymbolAddress((void**)&K16,  g_K16);
    cudaGetSymbolAddress((void**)&V,    g_V);
    cudaGetSymbolAddress((void**)&Vt,   g_Vt);
    cudaGetSymbolAddress((void**)&S,    g_S);
    cudaGetSymbolAddress((void**)&P,    g_P);
    cudaGetSymbolAddress((void**)&O16,  g_O16);
    cudaGetSymbolAddress((void**)&CS,   g_CS);

    cudaFuncSetAttribute(gemm_h<1,0,1>, cudaFuncAttributeMaxDynamicSharedMemorySize, SMEM_DYN);
    cudaFuncSetAttribute(gemm_h<0,0,0>, cudaFuncAttributeMaxDynamicSharedMemorySize, SMEM_DYN);
    cudaFuncSetAttribute(gemm_h<0,1,0>, cudaFuncAttributeMaxDynamicSharedMemorySize, SMEM_DYN);
    cudaFuncSetAttribute(gemm_h<0,2,1>, cudaFuncAttributeMaxDynamicSharedMemorySize, SMEM_DYN);

    dim3 gblk(128);
    dim3 blk(256);

    // launch 0: fused converts + rope table
    prepass_k<<<PRE_ITEMS / 256, blk>>>(
        (const float4*)x, (const float4*)Wq, (const float4*)Wk,
        (const float4*)Wv, (const float4*)Wf,
        X16, Wq16, Wk16, Wv16, Wf16, CS);

    dim3 gProj(CDIM / 128, MTOT / 128, 1);   // 8 x 64

    // launch 1: Q ; launch 2: K
    gemm_h<1,0,1><<<gProj, gblk, SMEM_DYN>>>(X16, Wq16, bq, CS, nullptr, Q16,
                                             CDIM, CDIM, 0, 0, 0, 1.0f);
    gemm_h<1,0,1><<<gProj, gblk, SMEM_DYN>>>(X16, Wk16, bk, CS, nullptr, K16,
                                             CDIM, CDIM, 0, 0, 0, 1.0f);

    // launch 3 (ncu target): S = Q K^T / 32, causal tile-skip
    dim3 gS(TSEQ / 128, TSEQ / 128, BSZ);    // 16 x 16 x 4
    gemm_h<0,1,0><<<gS, gblk, SMEM_DYN>>>(Q16, K16, nullptr, nullptr, S, nullptr,
                                          TSEQ, CDIM,
                                          (long)TSEQ * CDIM, (long)TSEQ * CDIM,
                                          (long)TSEQ * TSEQ, 1.0f / 32.0f);

    // launch 4: V projection (fp32 out)
    gemm_h<0,0,0><<<gProj, gblk, SMEM_DYN>>>(X16, Wv16, bv, nullptr, V, nullptr,
                                             CDIM, CDIM, 0, 0, 0, 1.0f);
    // launch 5: V transpose+convert
    dim3 gT(TSEQ / 32, CDIM / 32, BSZ);
    tcvt_v_k<<<gT, dim3(32, 8)>>>(V, Vt);

    // launch 6: softmax
    softmax_h_k<<<BSZ * TSEQ, blk>>>(S, P);

    // launch 7: O = P V (causal k-limit) -> fp16
    dim3 gPV(CDIM / 128, TSEQ / 128, BSZ);   // 8 x 16 x 4
    gemm_h<0,2,1><<<gPV, gblk, SMEM_DYN>>>(P, Vt, nullptr, nullptr, nullptr, O16,
                                           CDIM, TSEQ,
                                           (long)TSEQ * TSEQ, (long)CDIM * TSEQ,
                                           (long)TSEQ * CDIM, 1.0f);

    // launch 8: out = O Wf^T + bf (fp32)
    gemm_h<0,0,0><<<gProj, gblk, SMEM_DYN>>>(O16, Wf16, bf, nullptr, out, nullptr,
                                             CDIM, CDIM, 0, 0, 0, 1.0f);
}

// round 11
// speedup vs baseline: 1.3479x; 1.1395x over previous
#include <cuda_runtime.h>
#include <cuda_fp16.h>
#include <math.h>
#include <cstdint>

#define BSZ  4
#define TSEQ 2048
#define CDIM 1024
#define MTOT (BSZ*TSEQ)

#define KC 32
#define LDP 40                         // padded row length (halfs)
#define TILE_BYTES (128*LDP*2)         // 10240 per matrix per stage
#define NSTAGE 4
#define SMEM_DYN (2*NSTAGE*TILE_BYTES) // 81920
#define LDT 136                        // transpose tile row stride (halfs)

// ------------------------- persistent scratch ------------------------------
__device__ __align__(16) __half g_X16[(size_t)MTOT*CDIM];
__device__ __align__(16) __half g_Wq16[(size_t)CDIM*CDIM];
__device__ __align__(16) __half g_Wk16[(size_t)CDIM*CDIM];
__device__ __align__(16) __half g_Wv16[(size_t)CDIM*CDIM];
__device__ __align__(16) __half g_Wf16[(size_t)CDIM*CDIM];
__device__ __align__(16) __half g_Q16[(size_t)MTOT*CDIM];
__device__ __align__(16) __half g_K16[(size_t)MTOT*CDIM];
__device__ __align__(16) __half g_Vt [(size_t)BSZ*CDIM*TSEQ];
__device__ __align__(16) float  g_S  [(size_t)BSZ*TSEQ*TSEQ];
__device__ __align__(16) __half g_P  [(size_t)BSZ*TSEQ*TSEQ];
__device__ __align__(16) __half g_O16[(size_t)MTOT*CDIM];
__device__ __align__(16) float2 g_CS [(size_t)TSEQ*(CDIM/2)];

// ------------------------------ ptx helpers --------------------------------
__device__ __forceinline__ uint32_t smem_u32(const void* p) {
    uint32_t a;
    asm("{ .reg .u64 t; cvta.to.shared.u64 t, %1; cvt.u32.u64 %0, t; }"
        : "=r"(a) : "l"(p));
    return a;
}
__device__ __forceinline__ void cp16(uint32_t dst, const void* src) {
    asm volatile("cp.async.cg.shared.global [%0], [%1], 16;" :: "r"(dst), "l"(src));
}
#define CP_COMMIT() asm volatile("cp.async.commit_group;")
#define CP_WAIT0()  asm volatile("cp.async.wait_group 0;")
#define CP_WAIT1()  asm volatile("cp.async.wait_group 1;")
#define CP_WAIT2()  asm volatile("cp.async.wait_group 2;")

__device__ __forceinline__ void ldm_x4(uint32_t* r, uint32_t addr) {
    asm volatile("ldmatrix.sync.aligned.m8n8.x4.shared.b16 {%0,%1,%2,%3}, [%4];"
                 : "=r"(r[0]), "=r"(r[1]), "=r"(r[2]), "=r"(r[3]) : "r"(addr));
}
__device__ __forceinline__ void mma16816h(float* c, const uint32_t* a, const uint32_t* b) {
    asm volatile("mma.sync.aligned.m16n8k16.row.col.f32.f16.f16.f32 "
                 "{%0,%1,%2,%3}, {%4,%5,%6,%7}, {%8,%9}, {%0,%1,%2,%3};"
                 : "+f"(c[0]), "+f"(c[1]), "+f"(c[2]), "+f"(c[3])
                 : "r"(a[0]), "r"(a[1]), "r"(a[2]), "r"(a[3]), "r"(b[0]), "r"(b[1]));
}
__device__ __forceinline__ uint32_t pack_h2(float x, float y) {
    __half2 h = __floats2half2_rn(x, y);
    return *(uint32_t*)&h;
}

// --------------------------- shared mainloop -------------------------------
// Computes 128x128 tile of A(m0) x B(n0)^T over k=[0,tot*KC) into acc.
// Requires: dynamic smem ring (NSTAGE stages of A+B), 128 threads.
#define GEMM_MAINLOOP(Aptr, Bptr, Kdim)                                       \
    uint32_t adst = a_s + (lrow * LDP + lc8 * 8) * 2;                         \
    uint32_t bdst = b_s + (lrow * LDP + lc8 * 8) * 2;                         \
    auto load = [&](int c) {                                                  \
        int k0 = c * KC;                                                      \
        int st = c % NSTAGE;                                                  \
        const __half* sa = (Aptr) + (size_t)(m0 + lrow) * (Kdim) + k0 + lc8 * 8; \
        const __half* sb = (Bptr) + (size_t)(n0 + lrow) * (Kdim) + k0 + lc8 * 8; \
        uint32_t off = (uint32_t)(st * TILE_BYTES);                           \
        _Pragma("unroll")                                                     \
        for (int i = 0; i < 4; i++) {                                         \
            cp16(adst + off + i * 32 * LDP * 2, sa + (size_t)(32 * i) * (Kdim)); \
            cp16(bdst + off + i * 32 * LDP * 2, sb + (size_t)(32 * i) * (Kdim)); \
        }                                                                     \
        CP_COMMIT();                                                          \
    };                                                                        \
    load(0);                                                                  \
    if (tot > 1) load(1);                                                     \
    if (tot > 2) load(2);                                                     \
    for (int c = 0; c < tot; c++) {                                           \
        int rem = tot - 1 - c;                                                \
        if (rem >= 2) { CP_WAIT2(); } else if (rem == 1) { CP_WAIT1(); }      \
        else { CP_WAIT0(); }                                                  \
        __syncthreads();                                                      \
        if (c + 3 < tot) load(c + 3);                                         \
        int st = c % NSTAGE;                                                  \
        uint32_t ab = a_s + st * TILE_BYTES;                                  \
        uint32_t bb = b_s + st * TILE_BYTES;                                  \
        _Pragma("unroll")                                                     \
        for (int kk = 0; kk < 2; kk++) {                                      \
            uint32_t afr[4][4], bfr[4][4];                                    \
            int ar = (lane & 7) + ((lane >> 3) & 1) * 8;                      \
            int ak = kk * 16 + (lane >> 4) * 8;                               \
            _Pragma("unroll")                                                 \
            for (int mi = 0; mi < 4; mi++)                                    \
                ldm_x4(afr[mi], ab + ((wm * 64 + mi * 16 + ar) * LDP + ak) * 2); \
            int brow = (lane & 7) + ((lane >> 4) & 1) * 8;                    \
            int bcol = kk * 16 + ((lane >> 3) & 1) * 8;                       \
            _Pragma("unroll")                                                 \
            for (int p = 0; p < 4; p++)                                       \
                ldm_x4(bfr[p], bb + ((wn * 64 + p * 16 + brow) * LDP + bcol) * 2); \
            _Pragma("unroll")                                                 \
            for (int mi = 0; mi < 4; mi++)                                    \
                _Pragma("unroll")                                             \
                for (int ni = 0; ni < 8; ni++)                                \
                    mma16816h(acc[mi][ni], afr[mi], &bfr[ni >> 1][(ni & 1) * 2]); \
        }                                                                     \
    }

// ---------------------------------------------------------------------------
// generic fp16 NT GEMM (QK / PV / out-proj).
// CMODE: 0 none, 1 causal tile-skip, 2 causal k-limit. OUT16: fp16/fp32 out.
// ---------------------------------------------------------------------------
template<int CMODE, int OUT16>
__global__ void __launch_bounds__(128, 2) gemm_h(
    const __half* __restrict__ A, const __half* __restrict__ B,
    const float* __restrict__ bias,
    float* __restrict__ Cf, __half* __restrict__ Ch,
    int N, int K, long sA, long sB, long sC, float scale)
{
    int m0 = blockIdx.y * 128, n0 = blockIdx.x * 128;
    if (CMODE == 1 && n0 > m0 + 127) return;
    long z = blockIdx.z;
    A += z * sA; B += z * sB;
    if (OUT16) Ch += z * sC; else Cf += z * sC;

    extern __shared__ __align__(16) char smem_raw[];
    uint32_t a_s = smem_u32(smem_raw);
    uint32_t b_s = a_s + NSTAGE * TILE_BYTES;

    int tid = threadIdx.x, lane = tid & 31, wid = tid >> 5;
    int wm = wid & 1, wn = wid >> 1;
    int lrow = tid >> 2, lc8 = tid & 3;

    int kmax = (CMODE == 2) ? (m0 + 128) : K;
    int tot = kmax / KC;

    float acc[4][8][4];
    #pragma unroll
    for (int i = 0; i < 4; i++)
        #pragma unroll
        for (int j = 0; j < 8; j++)
            #pragma unroll
            for (int q = 0; q < 4; q++) acc[i][j][q] = 0.f;

    GEMM_MAINLOOP(A, B, K)

    int gr = lane >> 2, qc = (lane & 3) * 2;
    #pragma unroll
    for (int mi = 0; mi < 4; mi++) {
        #pragma unroll
        for (int half_ = 0; half_ < 2; half_++) {
            int m = m0 + wm * 64 + mi * 16 + gr + half_ * 8;
            #pragma unroll
            for (int ni = 0; ni < 8; ni++) {
                int n = n0 + wn * 64 + ni * 8 + qc;
                float v0 = acc[mi][ni][half_ * 2 + 0] * scale;
                float v1 = acc[mi][ni][half_ * 2 + 1] * scale;
                if (bias) { v0 += bias[n]; v1 += bias[n + 1]; }
                if (OUT16) {
                    *(uint32_t*)&Ch[(size_t)m * N + n] = pack_h2(v0, v1);
                } else {
                    *(float2*)&Cf[(size_t)m * N + n] = make_float2(v0, v1);
                }
            }
        }
    }
}

// ---------------------------------------------------------------------------
// merged QKV projection: grid.x = 24 (bx>>3 -> 0:Q 1:K 2:V), grid.y = 64.
// Q/K: +bias, +RoPE, fp16 [M,C]. V: +bias, transpose epilogue -> Vt [B,C,T].
// ---------------------------------------------------------------------------
__global__ void __launch_bounds__(128, 2) gemm_qkv(
    const __half* __restrict__ X,
    const __half* __restrict__ Wq, const __half* __restrict__ Wk,
    const __half* __restrict__ Wv,
    const float* __restrict__ bq, const float* __restrict__ bk,
    const float* __restrict__ bv,
    const float2* __restrict__ cs,
    __half* __restrict__ Q, __half* __restrict__ Kd, __half* __restrict__ Vt)
{
    int bx = blockIdx.x;
    int tgt = bx >> 3;
    int n0 = (bx & 7) * 128;
    int m0 = blockIdx.y * 128;

    const __half* B = (tgt == 0) ? Wq : (tgt == 1) ? Wk : Wv;
    const float* bias = (tgt == 0) ? bq : (tgt == 1) ? bk : bv;

    extern __shared__ __align__(16) char smem_raw[];
    uint32_t a_s = smem_u32(smem_raw);
    uint32_t b_s = a_s + NSTAGE * TILE_BYTES;

    int tid = threadIdx.x, lane = tid & 31, wid = tid >> 5;
    int wm = wid & 1, wn = wid >> 1;
    int lrow = tid >> 2, lc8 = tid & 3;
    int tot = CDIM / KC;

    float acc[4][8][4];
    #pragma unroll
    for (int i = 0; i < 4; i++)
        #pragma unroll
        for (int j = 0; j < 8; j++)
            #pragma unroll
            for (int q = 0; q < 4; q++) acc[i][j][q] = 0.f;

    GEMM_MAINLOOP(X, B, CDIM)

    int gr = lane >> 2, qc = (lane & 3) * 2;

    if (tgt < 2) {
        __half* Ch = (tgt == 0) ? Q : Kd;
        #pragma unroll
        for (int mi = 0; mi < 4; mi++) {
            #pragma unroll
            for (int half_ = 0; half_ < 2; half_++) {
                int m = m0 + wm * 64 + mi * 16 + gr + half_ * 8;
                int t = m & (TSEQ - 1);
                #pragma unroll
                for (int ni = 0; ni < 8; ni++) {
                    int n = n0 + wn * 64 + ni * 8 + qc;
                    float v0 = acc[mi][ni][half_ * 2 + 0] + bias[n];
                    float v1 = acc[mi][ni][half_ * 2 + 1] + bias[n + 1];
                    float2 sc = cs[(size_t)t * (CDIM / 2) + (n >> 1)];
                    float a = v0, b = v1;
                    v0 = a * sc.x - b * sc.y;
                    v1 = b * sc.x + a * sc.y;
                    *(uint32_t*)&Ch[(size_t)m * CDIM + n] = pack_h2(v0, v1);
                }
            }
        }
    } else {
        // V: transpose through smem, write Vt[z][n][t] coalesced along t.
        __syncthreads();                       // mainloop smem ring is dead now
        __half* tr = (__half*)smem_raw;        // 128 x LDT halfs = 34 KB
        #pragma unroll
        for (int mi = 0; mi < 4; mi++) {
            #pragma unroll
            for (int half_ = 0; half_ < 2; half_++) {
                int ml = wm * 64 + mi * 16 + gr + half_ * 8;
                #pragma unroll
                for (int ni = 0; ni < 8; ni++) {
                    int nl = wn * 64 + ni * 8 + qc;
                    float v0 = acc[mi][ni][half_ * 2 + 0] + bias[n0 + nl];
                    float v1 = acc[mi][ni][half_ * 2 + 1] + bias[n0 + nl + 1];
                    tr[nl * LDT + ml]       = __float2half_rn(v0);
                    tr[(nl + 1) * LDT + ml] = __float2half_rn(v1);
                }
            }
        }
        __syncthreads();
        int z = m0 / TSEQ, t0 = m0 & (TSEQ - 1);
        const uint4* src = (const uint4*)(tr + tid * LDT);
        uint4* dst = (uint4*)(Vt + (size_t)z * CDIM * TSEQ
                              + (size_t)(n0 + tid) * TSEQ + t0);
        #pragma unroll
        for (int i = 0; i < 16; i++) dst[i] = src[i];
    }
}

// ---------------------------------------------------------------------------
// fused pre-pass: convert x + 4 weights to fp16, build RoPE table.
// ---------------------------------------------------------------------------
#define XW4   (MTOT*CDIM/4)            // 2M
#define WW4   (CDIM*CDIM/4)            // 256K
__global__ void __launch_bounds__(256) prepass_k(
    const float4* __restrict__ x,
    const float4* __restrict__ Wq, const float4* __restrict__ Wk,
    const float4* __restrict__ Wv, const float4* __restrict__ Wf,
    __half* __restrict__ X16,
    __half* __restrict__ Wq16, __half* __restrict__ Wk16,
    __half* __restrict__ Wv16, __half* __restrict__ Wf16,
    float2* __restrict__ cs)
{
    int idx = blockIdx.x * 256 + threadIdx.x;
    if (idx < XW4 + 4 * WW4) {
        const float4* src;
        __half* dst;
        int off;
        if (idx < XW4) { src = x; dst = X16; off = idx; }
        else {
            int sub = idx - XW4;
            int w = sub / WW4;
            off = sub - w * WW4;
            src = (w == 0) ? Wq : (w == 1) ? Wk : (w == 2) ? Wv : Wf;
            dst = (w == 0) ? Wq16 : (w == 1) ? Wk16 : (w == 2) ? Wv16 : Wf16;
        }
        float4 v = src[off];
        *(uint2*)&dst[(size_t)off * 4] = make_uint2(pack_h2(v.x, v.y), pack_h2(v.z, v.w));
    } else {
        int r = idx - (XW4 + 4 * WW4);       // 0 .. 1M-1
        int t = r >> 9;
        int p = r & 511;
        float freq = powf(10000.0f, -(float)(2 * p) / (float)CDIM);
        float ang = (float)t * freq;
        float s, c;
        sincosf(ang, &s, &c);
        cs[r] = make_float2(c, s);
    }
}
#define PRE_ITEMS (XW4 + 4*WW4 + TSEQ*(CDIM/2))

// causal softmax: fp32 scores (prefix only) -> fp16 probs, zero-padded to the
// row's 128-block boundary.
__global__ void __launch_bounds__(256) softmax_h_k(
    const float* __restrict__ S, __half* __restrict__ P)
{
    long row = blockIdx.x;
    long b = row >> 11;
    int  t = (int)(row & (TSEQ - 1));
    const float* p = S + (b << 22) + ((long)t << 11);
    __half* ph = P + (b << 22) + ((long)t << 11);
    int n = t + 1;
    int kend = ((t >> 7) + 1) << 7;
    int tid = threadIdx.x;

    float4 v[2];
    float mx = -INFINITY;
    #pragma unroll
    for (int i = 0; i < 2; i++) {
        int base = (tid + 256 * i) * 4;
        if (base < n) {
            v[i] = *(const float4*)(p + base);
            float* f = (float*)&v[i];
            #pragma unroll
            for (int c = 0; c < 4; c++) {
                if (base + c >= n) f[c] = -INFINITY;
                mx = fmaxf(mx, f[c]);
            }
        } else {
            v[i] = make_float4(-INFINITY, -INFINITY, -INFINITY, -INFINITY);
        }
    }
    __shared__ float red[8];
    #pragma unroll
    for (int o = 16; o; o >>= 1) mx = fmaxf(mx, __shfl_xor_sync(~0u, mx, o));
    if ((tid & 31) == 0) red[tid >> 5] = mx;
    __syncthreads();
    mx = red[0];
    #pragma unroll
    for (int k = 1; k < 8; k++) mx = fmaxf(mx, red[k]);
    __syncthreads();

    float sum = 0.f;
    #pragma unroll
    for (int i = 0; i < 2; i++) {
        float* f = (float*)&v[i];
        #pragma unroll
        for (int c = 0; c < 4; c++) {
            float e = expf(f[c] - mx);
            f[c] = e;
            sum += e;
        }
    }
    #pragma unroll
    for (int o = 16; o; o >>= 1) sum += __shfl_xor_sync(~0u, sum, o);
    if ((tid & 31) == 0) red[tid >> 5] = sum;
    __syncthreads();
    sum = 0.f;
    #pragma unroll
    for (int k = 0; k < 8; k++) sum += red[k];
    float inv = 1.0f / sum;

    #pragma unroll
    for (int i = 0; i < 2; i++) {
        int base = (tid + 256 * i) * 4;
        if (base < kend) {
            float* f = (float*)&v[i];
            *(uint2*)(ph + base) =
                make_uint2(pack_h2(f[0] * inv, f[1] * inv),
                           pack_h2(f[2] * inv, f[3] * inv));
        }
    }
}

// ---------------------------------------------------------------------------
extern "C" void kernel_launch(void* const* d_in, const int* in_sizes, int n_in,
                              void* d_out, int out_size)
{
    const float* x  = (const float*)d_in[0];
    const float* Wq = (const float*)d_in[1];
    const float* bq = (const float*)d_in[2];
    const float* Wk = (const float*)d_in[3];
    const float* bk = (const float*)d_in[4];
    const float* Wv = (const float*)d_in[5];
    const float* bv = (const float*)d_in[6];
    const float* Wf = (const float*)d_in[7];
    const float* bf = (const float*)d_in[8];
    float* out = (float*)d_out;

    __half *X16,*Wq16,*Wk16,*Wv16,*Wf16,*Q16,*K16,*Vt,*P,*O16;
    float *S;
    float2* CS;
    cudaGetSymbolAddress((void**)&X16,  g_X16);
    cudaGetSymbolAddress((void**)&Wq16, g_Wq16);
    cudaGetSymbolAddress((void**)&Wk16, g_Wk16);
    cudaGetSymbolAddress((void**)&Wv16, g_Wv16);
    cudaGetSymbolAddress((void**)&Wf16, g_Wf16);
    cudaGetSymbolAddress((void**)&Q16,  g_Q16);
    cudaGetSymbolAddress((void**)&K16,  g_K16);
    cudaGetSymbolAddress((void**)&Vt,   g_Vt);
    cudaGetSymbolAddress((void**)&S,    g_S);
    cudaGetSymbolAddress((void**)&P,    g_P);
    cudaGetSymbolAddress((void**)&O16,  g_O16);
    cudaGetSymbolAddress((void**)&CS,   g_CS);

    cudaFuncSetAttribute(gemm_qkv,    cudaFuncAttributeMaxDynamicSharedMemorySize, SMEM_DYN);
    cudaFuncSetAttribute(gemm_h<1,0>, cudaFuncAttributeMaxDynamicSharedMemorySize, SMEM_DYN);
    cudaFuncSetAttribute(gemm_h<2,1>, cudaFuncAttributeMaxDynamicSharedMemorySize, SMEM_DYN);
    cudaFuncSetAttribute(gemm_h<0,0>, cudaFuncAttributeMaxDynamicSharedMemorySize, SMEM_DYN);

    dim3 gblk(128);
    dim3 blk(256);

    // launch 0: fused converts + rope table
    prepass_k<<<PRE_ITEMS / 256, blk>>>(
        (const float4*)x, (const float4*)Wq, (const float4*)Wk,
        (const float4*)Wv, (const float4*)Wf,
        X16, Wq16, Wk16, Wv16, Wf16, CS);

    // launch 1: merged Q/K/V projections (V written transposed)
    dim3 gQKV(24, MTOT / 128, 1);
    gemm_qkv<<<gQKV, gblk, SMEM_DYN>>>(X16, Wq16, Wk16, Wv16, bq, bk, bv, CS,
                                       Q16, K16, Vt);

    // launch 2: S = Q K^T / 32, causal tile-skip
    dim3 gS(TSEQ / 128, TSEQ / 128, BSZ);
    gemm_h<1,0><<<gS, gblk, SMEM_DYN>>>(Q16, K16, nullptr, S, nullptr,
                                        TSEQ, CDIM,
                                        (long)TSEQ * CDIM, (long)TSEQ * CDIM,
                                        (long)TSEQ * TSEQ, 1.0f / 32.0f);

    // launch 3: softmax
    softmax_h_k<<<BSZ * TSEQ, blk>>>(S, P);

    // launch 4: O = P V (causal k-limit) -> fp16
    dim3 gPV(CDIM / 128, TSEQ / 128, BSZ);
    gemm_h<2,1><<<gPV, gblk, SMEM_DYN>>>(P, Vt, nullptr, nullptr, O16,
                                         CDIM, TSEQ,
                                         (long)TSEQ * TSEQ, (long)CDIM * TSEQ,
                                         (long)TSEQ * CDIM, 1.0f);

    // launch 5: out = O Wf^T + bf (fp32)
    dim3 gOut(CDIM / 128, MTOT / 128, 1);
    gemm_h<0,0><<<gOut, gblk, SMEM_DYN>>>(O16, Wf16, bf, out, nullptr,
                                          CDIM, CDIM, 0, 0, 0, 1.0f);
}

// round 12
// speedup vs baseline: 1.3517x; 1.0028x over previous
#include <cuda_runtime.h>
#include <cuda_fp16.h>
#include <math.h>
#include <cstdint>

#define BSZ  4
#define TSEQ 2048
#define CDIM 1024
#define MTOT (BSZ*TSEQ)

#define KC 32
#define LDP 40                         // padded row length (halfs)
#define TILE_BYTES (128*LDP*2)         // 10240 per matrix per stage
#define NSTAGE 4
#define SMEM_DYN (2*NSTAGE*TILE_BYTES) // 81920
#define LDT 136                        // transpose tile row stride (halfs)

// ------------------------- persistent scratch ------------------------------
__device__ __align__(16) __half g_X16[(size_t)MTOT*CDIM];
__device__ __align__(16) __half g_Wq16[(size_t)CDIM*CDIM];
__device__ __align__(16) __half g_Wk16[(size_t)CDIM*CDIM];
__device__ __align__(16) __half g_Wv16[(size_t)CDIM*CDIM];
__device__ __align__(16) __half g_Wf16[(size_t)CDIM*CDIM];
__device__ __align__(16) __half g_Q16[(size_t)MTOT*CDIM];
__device__ __align__(16) __half g_K16[(size_t)MTOT*CDIM];
__device__ __align__(16) __half g_Vt [(size_t)BSZ*CDIM*TSEQ];
__device__ __align__(16) float  g_S  [(size_t)BSZ*TSEQ*TSEQ];
__device__ __align__(16) __half g_P  [(size_t)BSZ*TSEQ*TSEQ];
__device__ __align__(16) __half g_O16[(size_t)MTOT*CDIM];
__device__ __align__(16) float2 g_CS [(size_t)TSEQ*(CDIM/2)];

// ------------------------------ ptx helpers --------------------------------
__device__ __forceinline__ uint32_t smem_u32(const void* p) {
    uint32_t a;
    asm("{ .reg .u64 t; cvta.to.shared.u64 t, %1; cvt.u32.u64 %0, t; }"
        : "=r"(a) : "l"(p));
    return a;
}
__device__ __forceinline__ void cp16(uint32_t dst, const void* src) {
    asm volatile("cp.async.cg.shared.global [%0], [%1], 16;" :: "r"(dst), "l"(src));
}
#define CP_COMMIT() asm volatile("cp.async.commit_group;")
#define CP_WAIT0()  asm volatile("cp.async.wait_group 0;")
#define CP_WAIT1()  asm volatile("cp.async.wait_group 1;")
#define CP_WAIT2()  asm volatile("cp.async.wait_group 2;")

__device__ __forceinline__ void ldm_x4(uint32_t* r, uint32_t addr) {
    asm volatile("ldmatrix.sync.aligned.m8n8.x4.shared.b16 {%0,%1,%2,%3}, [%4];"
                 : "=r"(r[0]), "=r"(r[1]), "=r"(r[2]), "=r"(r[3]) : "r"(addr));
}
__device__ __forceinline__ void mma16816h(float* c, const uint32_t* a, const uint32_t* b) {
    asm volatile("mma.sync.aligned.m16n8k16.row.col.f32.f16.f16.f32 "
                 "{%0,%1,%2,%3}, {%4,%5,%6,%7}, {%8,%9}, {%0,%1,%2,%3};"
                 : "+f"(c[0]), "+f"(c[1]), "+f"(c[2]), "+f"(c[3])
                 : "r"(a[0]), "r"(a[1]), "r"(a[2]), "r"(a[3]), "r"(b[0]), "r"(b[1]));
}
__device__ __forceinline__ uint32_t pack_h2(float x, float y) {
    __half2 h = __floats2half2_rn(x, y);
    return *(uint32_t*)&h;
}

// --------------------------- shared mainloop -------------------------------
#define GEMM_MAINLOOP(Aptr, Bptr, Kdim)                                       \
    uint32_t adst = a_s + (lrow * LDP + lc8 * 8) * 2;                         \
    uint32_t bdst = b_s + (lrow * LDP + lc8 * 8) * 2;                         \
    auto load = [&](int c) {                                                  \
        int k0 = c * KC;                                                      \
        int st = c % NSTAGE;                                                  \
        const __half* sa = (Aptr) + (size_t)(m0 + lrow) * (Kdim) + k0 + lc8 * 8; \
        const __half* sb = (Bptr) + (size_t)(n0 + lrow) * (Kdim) + k0 + lc8 * 8; \
        uint32_t off = (uint32_t)(st * TILE_BYTES);                           \
        _Pragma("unroll")                                                     \
        for (int i = 0; i < 4; i++) {                                         \
            cp16(adst + off + i * 32 * LDP * 2, sa + (size_t)(32 * i) * (Kdim)); \
            cp16(bdst + off + i * 32 * LDP * 2, sb + (size_t)(32 * i) * (Kdim)); \
        }                                                                     \
        CP_COMMIT();                                                          \
    };                                                                        \
    load(0);                                                                  \
    if (tot > 1) load(1);                                                     \
    if (tot > 2) load(2);                                                     \
    for (int c = 0; c < tot; c++) {                                           \
        int rem = tot - 1 - c;                                                \
        if (rem >= 2) { CP_WAIT2(); } else if (rem == 1) { CP_WAIT1(); }      \
        else { CP_WAIT0(); }                                                  \
        __syncthreads();                                                      \
        if (c + 3 < tot) load(c + 3);                                         \
        int st = c % NSTAGE;                                                  \
        uint32_t ab = a_s + st * TILE_BYTES;                                  \
        uint32_t bb = b_s + st * TILE_BYTES;                                  \
        _Pragma("unroll")                                                     \
        for (int kk = 0; kk < 2; kk++) {                                      \
            uint32_t afr[4][4], bfr[4][4];                                    \
            int ar = (lane & 7) + ((lane >> 3) & 1) * 8;                      \
            int ak = kk * 16 + (lane >> 4) * 8;                               \
            _Pragma("unroll")                                                 \
            for (int mi = 0; mi < 4; mi++)                                    \
                ldm_x4(afr[mi], ab + ((wm * 64 + mi * 16 + ar) * LDP + ak) * 2); \
            int brow = (lane & 7) + ((lane >> 4) & 1) * 8;                    \
            int bcol = kk * 16 + ((lane >> 3) & 1) * 8;                       \
            _Pragma("unroll")                                                 \
            for (int p = 0; p < 4; p++)                                       \
                ldm_x4(bfr[p], bb + ((wn * 64 + p * 16 + brow) * LDP + bcol) * 2); \
            _Pragma("unroll")                                                 \
            for (int mi = 0; mi < 4; mi++)                                    \
                _Pragma("unroll")                                             \
                for (int ni = 0; ni < 8; ni++)                                \
                    mma16816h(acc[mi][ni], afr[mi], &bfr[ni >> 1][(ni & 1) * 2]); \
        }                                                                     \
    }

// ---------------------------------------------------------------------------
// generic fp16 NT GEMM (QK / PV / out-proj).
// CMODE: 0 none, 1 causal TRIANGULAR-PACKED grid (blockIdx.x = linear lower-
// triangle tile id), 2 causal k-limit. OUT16: fp16/fp32 out.
// ---------------------------------------------------------------------------
template<int CMODE, int OUT16>
__global__ void __launch_bounds__(128, 2) gemm_h(
    const __half* __restrict__ A, const __half* __restrict__ B,
    const float* __restrict__ bias,
    float* __restrict__ Cf, __half* __restrict__ Ch,
    int N, int K, long sA, long sB, long sC, float scale)
{
    int m0, n0;
    if (CMODE == 1) {
        int l = blockIdx.x;                      // 0 .. 135 (16*17/2 - 1)
        int ti = (int)((sqrtf(8.f * l + 1.f) - 1.f) * 0.5f);
        while ((ti + 1) * (ti + 2) / 2 <= l) ti++;
        while (ti * (ti + 1) / 2 > l) ti--;
        m0 = ti * 128;
        n0 = (l - ti * (ti + 1) / 2) * 128;
    } else {
        m0 = blockIdx.y * 128;
        n0 = blockIdx.x * 128;
    }
    long z = blockIdx.z;
    A += z * sA; B += z * sB;
    if (OUT16) Ch += z * sC; else Cf += z * sC;

    extern __shared__ __align__(16) char smem_raw[];
    uint32_t a_s = smem_u32(smem_raw);
    uint32_t b_s = a_s + NSTAGE * TILE_BYTES;

    int tid = threadIdx.x, lane = tid & 31, wid = tid >> 5;
    int wm = wid & 1, wn = wid >> 1;
    int lrow = tid >> 2, lc8 = tid & 3;

    int kmax = (CMODE == 2) ? (m0 + 128) : K;
    int tot = kmax / KC;

    float acc[4][8][4];
    #pragma unroll
    for (int i = 0; i < 4; i++)
        #pragma unroll
        for (int j = 0; j < 8; j++)
            #pragma unroll
            for (int q = 0; q < 4; q++) acc[i][j][q] = 0.f;

    GEMM_MAINLOOP(A, B, K)

    int gr = lane >> 2, qc = (lane & 3) * 2;
    #pragma unroll
    for (int mi = 0; mi < 4; mi++) {
        #pragma unroll
        for (int half_ = 0; half_ < 2; half_++) {
            int m = m0 + wm * 64 + mi * 16 + gr + half_ * 8;
            #pragma unroll
            for (int ni = 0; ni < 8; ni++) {
                int n = n0 + wn * 64 + ni * 8 + qc;
                float v0 = acc[mi][ni][half_ * 2 + 0] * scale;
                float v1 = acc[mi][ni][half_ * 2 + 1] * scale;
                if (bias) { v0 += bias[n]; v1 += bias[n + 1]; }
                if (OUT16) {
                    *(uint32_t*)&Ch[(size_t)m * N + n] = pack_h2(v0, v1);
                } else {
                    *(float2*)&Cf[(size_t)m * N + n] = make_float2(v0, v1);
                }
            }
        }
    }
}

// ---------------------------------------------------------------------------
// merged QKV projection: grid.x = 24 (bx>>3 -> 0:Q 1:K 2:V), grid.y = 64.
// Q/K: +bias, +RoPE, fp16 [M,C]. V: +bias, transpose epilogue -> Vt [B,C,T].
// ---------------------------------------------------------------------------
__global__ void __launch_bounds__(128, 2) gemm_qkv(
    const __half* __restrict__ X,
    const __half* __restrict__ Wq, const __half* __restrict__ Wk,
    const __half* __restrict__ Wv,
    const float* __restrict__ bq, const float* __restrict__ bk,
    const float* __restrict__ bv,
    const float2* __restrict__ cs,
    __half* __restrict__ Q, __half* __restrict__ Kd, __half* __restrict__ Vt)
{
    int bx = blockIdx.x;
    int tgt = bx >> 3;
    int n0 = (bx & 7) * 128;
    int m0 = blockIdx.y * 128;

    const __half* B = (tgt == 0) ? Wq : (tgt == 1) ? Wk : Wv;
    const float* bias = (tgt == 0) ? bq : (tgt == 1) ? bk : bv;

    extern __shared__ __align__(16) char smem_raw[];
    uint32_t a_s = smem_u32(smem_raw);
    uint32_t b_s = a_s + NSTAGE * TILE_BYTES;

    int tid = threadIdx.x, lane = tid & 31, wid = tid >> 5;
    int wm = wid & 1, wn = wid >> 1;
    int lrow = tid >> 2, lc8 = tid & 3;
    int tot = CDIM / KC;

    float acc[4][8][4];
    #pragma unroll
    for (int i = 0; i < 4; i++)
        #pragma unroll
        for (int j = 0; j < 8; j++)
            #pragma unroll
            for (int q = 0; q < 4; q++) acc[i][j][q] = 0.f;

    GEMM_MAINLOOP(X, B, CDIM)

    int gr = lane >> 2, qc = (lane & 3) * 2;

    if (tgt < 2) {
        __half* Ch = (tgt == 0) ? Q : Kd;
        #pragma unroll
        for (int mi = 0; mi < 4; mi++) {
            #pragma unroll
            for (int half_ = 0; half_ < 2; half_++) {
                int m = m0 + wm * 64 + mi * 16 + gr + half_ * 8;
                int t = m & (TSEQ - 1);
                #pragma unroll
                for (int ni = 0; ni < 8; ni++) {
                    int n = n0 + wn * 64 + ni * 8 + qc;
                    float v0 = acc[mi][ni][half_ * 2 + 0] + bias[n];
                    float v1 = acc[mi][ni][half_ * 2 + 1] + bias[n + 1];
                    float2 sc = cs[(size_t)t * (CDIM / 2) + (n >> 1)];
                    float a = v0, b = v1;
                    v0 = a * sc.x - b * sc.y;
                    v1 = b * sc.x + a * sc.y;
                    *(uint32_t*)&Ch[(size_t)m * CDIM + n] = pack_h2(v0, v1);
                }
            }
        }
    } else {
        // V: transpose through smem, write Vt[z][n][t] coalesced along t.
        __syncthreads();                       // mainloop smem ring is dead now
        __half* tr = (__half*)smem_raw;        // 128 x LDT halfs = 34 KB
        #pragma unroll
        for (int mi = 0; mi < 4; mi++) {
            #pragma unroll
            for (int half_ = 0; half_ < 2; half_++) {
                int ml = wm * 64 + mi * 16 + gr + half_ * 8;
                #pragma unroll
                for (int ni = 0; ni < 8; ni++) {
                    int nl = wn * 64 + ni * 8 + qc;
                    float v0 = acc[mi][ni][half_ * 2 + 0] + bias[n0 + nl];
                    float v1 = acc[mi][ni][half_ * 2 + 1] + bias[n0 + nl + 1];
                    tr[nl * LDT + ml]       = __float2half_rn(v0);
                    tr[(nl + 1) * LDT + ml] = __float2half_rn(v1);
                }
            }
        }
        __syncthreads();
        int z = m0 / TSEQ, t0 = m0 & (TSEQ - 1);
        const uint4* src = (const uint4*)(tr + tid * LDT);
        uint4* dst = (uint4*)(Vt + (size_t)z * CDIM * TSEQ
                              + (size_t)(n0 + tid) * TSEQ + t0);
        #pragma unroll
        for (int i = 0; i < 16; i++) dst[i] = src[i];
    }
}

// ---------------------------------------------------------------------------
// fused pre-pass: convert x + 4 weights to fp16, build RoPE table.
// 4 grid-strided items per thread for MLP; exp2f instead of powf.
// ---------------------------------------------------------------------------
#define XW4   (MTOT*CDIM/4)            // 2M float4 items
#define WW4   (CDIM*CDIM/4)            // 256K
#define CVT_ITEMS (XW4 + 4*WW4)        // 3M
#define ROPE_ITEMS (TSEQ*(CDIM/2))     // 1M
#define PRE_TOTAL (CVT_ITEMS + ROPE_ITEMS)
#define PRE_BLOCKS (PRE_TOTAL / (256*4))

__global__ void __launch_bounds__(256) prepass_k(
    const float4* __restrict__ x,
    const float4* __restrict__ Wq, const float4* __restrict__ Wk,
    const float4* __restrict__ Wv, const float4* __restrict__ Wf,
    __half* __restrict__ X16,
    __half* __restrict__ Wq16, __half* __restrict__ Wk16,
    __half* __restrict__ Wv16, __half* __restrict__ Wf16,
    float2* __restrict__ cs)
{
    int base = blockIdx.x * 256 + threadIdx.x;
    const int stride = PRE_BLOCKS * 256;
    #pragma unroll
    for (int it = 0; it < 4; it++) {
        int idx = base + it * stride;
        if (idx < CVT_ITEMS) {
            const float4* src;
            __half* dst;
            int off;
            if (idx < XW4) { src = x; dst = X16; off = idx; }
            else {
                int sub = idx - XW4;
                int w = sub / WW4;
                off = sub - w * WW4;
                src = (w == 0) ? Wq : (w == 1) ? Wk : (w == 2) ? Wv : Wf;
                dst = (w == 0) ? Wq16 : (w == 1) ? Wk16 : (w == 2) ? Wv16 : Wf16;
            }
            float4 v = src[off];
            *(uint2*)&dst[(size_t)off * 4] =
                make_uint2(pack_h2(v.x, v.y), pack_h2(v.z, v.w));
        } else {
            int r = idx - CVT_ITEMS;             // 0 .. 1M-1
            int t = r >> 9;
            int p = r & 511;
            // 10000^(-2p/d) = exp2(-(2p/d) * log2(10000))
            float freq = exp2f(-(float)(2 * p) * (13.28771238f / (float)CDIM));
            float ang = (float)t * freq;
            float s, c;
            sincosf(ang, &s, &c);
            cs[r] = make_float2(c, s);
        }
    }
}

// causal softmax: fp32 scores (prefix only) -> fp16 probs, zero-padded to the
// row's 128-block boundary. __expf: error ~1e-7 rel, negligible vs fp16 P.
__global__ void __launch_bounds__(256) softmax_h_k(
    const float* __restrict__ S, __half* __restrict__ P)
{
    long row = blockIdx.x;
    long b = row >> 11;
    int  t = (int)(row & (TSEQ - 1));
    const float* p = S + (b << 22) + ((long)t << 11);
    __half* ph = P + (b << 22) + ((long)t << 11);
    int n = t + 1;
    int kend = ((t >> 7) + 1) << 7;
    int tid = threadIdx.x;

    float4 v[2];
    float mx = -INFINITY;
    #pragma unroll
    for (int i = 0; i < 2; i++) {
        int base = (tid + 256 * i) * 4;
        if (base < n) {
            v[i] = *(const float4*)(p + base);
            float* f = (float*)&v[i];
            #pragma unroll
            for (int c = 0; c < 4; c++) {
                if (base + c >= n) f[c] = -INFINITY;
                mx = fmaxf(mx, f[c]);
            }
        } else {
            v[i] = make_float4(-INFINITY, -INFINITY, -INFINITY, -INFINITY);
        }
    }
    __shared__ float red[8];
    #pragma unroll
    for (int o = 16; o; o >>= 1) mx = fmaxf(mx, __shfl_xor_sync(~0u, mx, o));
    if ((tid & 31) == 0) red[tid >> 5] = mx;
    __syncthreads();
    mx = red[0];
    #pragma unroll
    for (int k = 1; k < 8; k++) mx = fmaxf(mx, red[k]);
    __syncthreads();

    float sum = 0.f;
    #pragma unroll
    for (int i = 0; i < 2; i++) {
        float* f = (float*)&v[i];
        #pragma unroll
        for (int c = 0; c < 4; c++) {
            float e = (f[c] == -INFINITY) ? 0.f : __expf(f[c] - mx);
            f[c] = e;
            sum += e;
        }
    }
    #pragma unroll
    for (int o = 16; o; o >>= 1) sum += __shfl_xor_sync(~0u, sum, o);
    if ((tid & 31) == 0) red[tid >> 5] = sum;
    __syncthreads();
    sum = 0.f;
    #pragma unroll
    for (int k = 0; k < 8; k++) sum += red[k];
    float inv = 1.0f / sum;

    #pragma unroll
    for (int i = 0; i < 2; i++) {
        int base = (tid + 256 * i) * 4;
        if (base < kend) {
            float* f = (float*)&v[i];
            *(uint2*)(ph + base) =
                make_uint2(pack_h2(f[0] * inv, f[1] * inv),
                           pack_h2(f[2] * inv, f[3] * inv));
        }
    }
}

// ---------------------------------------------------------------------------
extern "C" void kernel_launch(void* const* d_in, const int* in_sizes, int n_in,
                              void* d_out, int out_size)
{
    const float* x  = (const float*)d_in[0];
    const float* Wq = (const float*)d_in[1];
    const float* bq = (const float*)d_in[2];
    const float* Wk = (const float*)d_in[3];
    const float* bk = (const float*)d_in[4];
    const float* Wv = (const float*)d_in[5];
    const float* bv = (const float*)d_in[6];
    const float* Wf = (const float*)d_in[7];
    const float* bf = (const float*)d_in[8];
    float* out = (float*)d_out;

    __half *X16,*Wq16,*Wk16,*Wv16,*Wf16,*Q16,*K16,*Vt,*P,*O16;
    float *S;
    float2* CS;
    cudaGetSymbolAddress((void**)&X16,  g_X16);
    cudaGetSymbolAddress((void**)&Wq16, g_Wq16);
    cudaGetSymbolAddress((void**)&Wk16, g_Wk16);
    cudaGetSymbolAddress((void**)&Wv16, g_Wv16);
    cudaGetSymbolAddress((void**)&Wf16, g_Wf16);
    cudaGetSymbolAddress((void**)&Q16,  g_Q16);
    cudaGetSymbolAddress((void**)&K16,  g_K16);
    cudaGetSymbolAddress((void**)&Vt,   g_Vt);
    cudaGetSymbolAddress((void**)&S,    g_S);
    cudaGetSymbolAddress((void**)&P,    g_P);
    cudaGetSymbolAddress((void**)&O16,  g_O16);
    cudaGetSymbolAddress((void**)&CS,   g_CS);

    cudaFuncSetAttribute(gemm_qkv,    cudaFuncAttributeMaxDynamicSharedMemorySize, SMEM_DYN);
    cudaFuncSetAttribute(gemm_h<1,0>, cudaFuncAttributeMaxDynamicSharedMemorySize, SMEM_DYN);
    cudaFuncSetAttribute(gemm_h<2,1>, cudaFuncAttributeMaxDynamicSharedMemorySize, SMEM_DYN);
    cudaFuncSetAttribute(gemm_h<0,0>, cudaFuncAttributeMaxDynamicSharedMemorySize, SMEM_DYN);

    dim3 gblk(128);
    dim3 blk(256);

    // launch 0: fused converts + rope table (4 items/thread)
    prepass_k<<<PRE_BLOCKS, blk>>>(
        (const float4*)x, (const float4*)Wq, (const float4*)Wk,
        (const float4*)Wv, (const float4*)Wf,
        X16, Wq16, Wk16, Wv16, Wf16, CS);

    // launch 1: merged Q/K/V projections (V written transposed)
    dim3 gQKV(24, MTOT / 128, 1);
    gemm_qkv<<<gQKV, gblk, SMEM_DYN>>>(X16, Wq16, Wk16, Wv16, bq, bk, bv, CS,
                                       Q16, K16, Vt);

    // launch 2: S = Q K^T / 32, triangular-packed causal grid (136 tiles)
    dim3 gS(136, 1, BSZ);
    gemm_h<1,0><<<gS, gblk, SMEM_DYN>>>(Q16, K16, nullptr, S, nullptr,
                                        TSEQ, CDIM,
                                        (long)TSEQ * CDIM, (long)TSEQ * CDIM,
                                        (long)TSEQ * TSEQ, 1.0f / 32.0f);

    // launch 3: softmax
    softmax_h_k<<<BSZ * TSEQ, blk>>>(S, P);

    // launch 4: O = P V (causal k-limit) -> fp16
    dim3 gPV(CDIM / 128, TSEQ / 128, BSZ);
    gemm_h<2,1><<<gPV, gblk, SMEM_DYN>>>(P, Vt, nullptr, nullptr, O16,
                                         CDIM, TSEQ,
                                         (long)TSEQ * TSEQ, (long)CDIM * TSEQ,
                                         (long)TSEQ * CDIM, 1.0f);

    // launch 5: out = O Wf^T + bf (fp32)
    dim3 gOut(CDIM / 128, MTOT / 128, 1);
    gemm_h<0,0><<<gOut, gblk, SMEM_DYN>>>(O16, Wf16, bf, out, nullptr,
                                          CDIM, CDIM, 0, 0, 0, 1.0f);
}

// round 14
// speedup vs baseline: 1.4003x; 1.0360x over previous
#include <cuda_runtime.h>
#include <cuda_fp16.h>
#include <math.h>
#include <cstdint>

#define BSZ  4
#define TSEQ 2048
#define CDIM 1024
#define MTOT (BSZ*TSEQ)

#define KC 32
#define LDP 40                         // padded row length (halfs)
#define TILE_BYTES (128*LDP*2)         // 10240 per matrix per stage
#define NSTAGE 4
#define SMEM_DYN (2*NSTAGE*TILE_BYTES) // 81920
#define LDT 136                        // transpose tile row stride (halfs)

// ------------------------- persistent scratch ------------------------------
__device__ __align__(16) __half g_X16[(size_t)MTOT*CDIM];
__device__ __align__(16) __half g_Wq16[(size_t)CDIM*CDIM];
__device__ __align__(16) __half g_Wk16[(size_t)CDIM*CDIM];
__device__ __align__(16) __half g_Wv16[(size_t)CDIM*CDIM];
__device__ __align__(16) __half g_Wf16[(size_t)CDIM*CDIM];
__device__ __align__(16) __half g_Q16[(size_t)MTOT*CDIM];
__device__ __align__(16) __half g_K16[(size_t)MTOT*CDIM];
__device__ __align__(16) __half g_Vt [(size_t)BSZ*CDIM*TSEQ];
__device__ __align__(16) float  g_S  [(size_t)BSZ*TSEQ*TSEQ];
__device__ __align__(16) __half g_P  [(size_t)BSZ*TSEQ*TSEQ];
__device__ __align__(16) __half g_O16[(size_t)MTOT*CDIM];
__device__ __align__(16) float2 g_CS [(size_t)TSEQ*(CDIM/2)];

// ------------------------------ ptx helpers --------------------------------
__device__ __forceinline__ uint32_t smem_u32(const void* p) {
    uint32_t a;
    asm("{ .reg .u64 t; cvta.to.shared.u64 t, %1; cvt.u32.u64 %0, t; }"
        : "=r"(a) : "l"(p));
    return a;
}
__device__ __forceinline__ void cp16(uint32_t dst, const void* src) {
    asm volatile("cp.async.cg.shared.global [%0], [%1], 16;" :: "r"(dst), "l"(src));
}
#define CP_COMMIT() asm volatile("cp.async.commit_group;")
#define CP_WAIT0()  asm volatile("cp.async.wait_group 0;")
#define CP_WAIT1()  asm volatile("cp.async.wait_group 1;")
#define CP_WAIT2()  asm volatile("cp.async.wait_group 2;")

__device__ __forceinline__ void ldm_x4(uint32_t* r, uint32_t addr) {
    asm volatile("ldmatrix.sync.aligned.m8n8.x4.shared.b16 {%0,%1,%2,%3}, [%4];"
                 : "=r"(r[0]), "=r"(r[1]), "=r"(r[2]), "=r"(r[3]) : "r"(addr));
}
__device__ __forceinline__ void mma16816h(float* c, const uint32_t* a, const uint32_t* b) {
    asm volatile("mma.sync.aligned.m16n8k16.row.col.f32.f16.f16.f32 "
                 "{%0,%1,%2,%3}, {%4,%5,%6,%7}, {%8,%9}, {%0,%1,%2,%3};"
                 : "+f"(c[0]), "+f"(c[1]), "+f"(c[2]), "+f"(c[3])
                 : "r"(a[0]), "r"(a[1]), "r"(a[2]), "r"(a[3]), "r"(b[0]), "r"(b[1]));
}
__device__ __forceinline__ uint32_t pack_h2(float x, float y) {
    __half2 h = __floats2half2_rn(x, y);
    return *(uint32_t*)&h;
}

// --------------------------- shared mainloop -------------------------------
#define GEMM_MAINLOOP(Aptr, Bptr, Kdim)                                       \
    uint32_t adst = a_s + (lrow * LDP + lc8 * 8) * 2;                         \
    uint32_t bdst = b_s + (lrow * LDP + lc8 * 8) * 2;                         \
    auto load = [&](int c) {                                                  \
        int k0 = c * KC;                                                      \
        int st = c % NSTAGE;                                                  \
        const __half* sa = (Aptr) + (size_t)(m0 + lrow) * (Kdim) + k0 + lc8 * 8; \
        const __half* sb = (Bptr) + (size_t)(n0 + lrow) * (Kdim) + k0 + lc8 * 8; \
        uint32_t off = (uint32_t)(st * TILE_BYTES);                           \
        _Pragma("unroll")                                                     \
        for (int i = 0; i < 4; i++) {                                         \
            cp16(adst + off + i * 32 * LDP * 2, sa + (size_t)(32 * i) * (Kdim)); \
            cp16(bdst + off + i * 32 * LDP * 2, sb + (size_t)(32 * i) * (Kdim)); \
        }                                                                     \
        CP_COMMIT();                                                          \
    };                                                                        \
    load(0);                                                                  \
    if (tot > 1) load(1);                                                     \
    if (tot > 2) load(2);                                                     \
    for (int c = 0; c < tot; c++) {                                           \
        int rem = tot - 1 - c;                                                \
        if (rem >= 2) { CP_WAIT2(); } else if (rem == 1) { CP_WAIT1(); }      \
        else { CP_WAIT0(); }                                                  \
        __syncthreads();                                                      \
        if (c + 3 < tot) load(c + 3);                                         \
        int st = c % NSTAGE;                                                  \
        uint32_t ab = a_s + st * TILE_BYTES;                                  \
        uint32_t bb = b_s + st * TILE_BYTES;                                  \
        _Pragma("unroll")                                                     \
        for (int kk = 0; kk < 2; kk++) {                                      \
            uint32_t afr[4][4], bfr[4][4];                                    \
            int ar = (lane & 7) + ((lane >> 3) & 1) * 8;                      \
            int ak = kk * 16 + (lane >> 4) * 8;                               \
            _Pragma("unroll")                                                 \
            for (int mi = 0; mi < 4; mi++)                                    \
                ldm_x4(afr[mi], ab + ((wm * 64 + mi * 16 + ar) * LDP + ak) * 2); \
            int brow = (lane & 7) + ((lane >> 4) & 1) * 8;                    \
            int bcol = kk * 16 + ((lane >> 3) & 1) * 8;                       \
            _Pragma("unroll")                                                 \
            for (int p = 0; p < 4; p++)                                       \
                ldm_x4(bfr[p], bb + ((wn * 64 + p * 16 + brow) * LDP + bcol) * 2); \
            _Pragma("unroll")                                                 \
            for (int mi = 0; mi < 4; mi++)                                    \
                _Pragma("unroll")                                             \
                for (int ni = 0; ni < 8; ni++)                                \
                    mma16816h(acc[mi][ni], afr[mi], &bfr[ni >> 1][(ni & 1) * 2]); \
        }                                                                     \
    }

// ---------------------------------------------------------------------------
// generic fp16 NT GEMM (QK / PV / out-proj).
// CMODE: 0 none, 1 causal TRIANGULAR-PACKED grid, 2 causal k-limit with
// heavy-first row ordering. OUT16: fp16/fp32 out.
// ---------------------------------------------------------------------------
template<int CMODE, int OUT16>
__global__ void __launch_bounds__(128, 2) gemm_h(
    const __half* __restrict__ A, const __half* __restrict__ B,
    const float* __restrict__ bias,
    float* __restrict__ Cf, __half* __restrict__ Ch,
    int N, int K, long sA, long sB, long sC, float scale)
{
    int m0, n0;
    if (CMODE == 1) {
        int l = blockIdx.x;                      // 0 .. 135 (16*17/2 - 1)
        int ti = (int)((sqrtf(8.f * l + 1.f) - 1.f) * 0.5f);
        while ((ti + 1) * (ti + 2) / 2 <= l) ti++;
        while (ti * (ti + 1) / 2 > l) ti--;
        m0 = ti * 128;
        n0 = (l - ti * (ti + 1) / 2) * 128;
    } else if (CMODE == 2) {
        m0 = (gridDim.y - 1 - blockIdx.y) * 128;   // heavy tiles first (LPT)
        n0 = blockIdx.x * 128;
    } else {
        m0 = blockIdx.y * 128;
        n0 = blockIdx.x * 128;
    }
    long z = blockIdx.z;
    A += z * sA; B += z * sB;
    if (OUT16) Ch += z * sC; else Cf += z * sC;

    extern __shared__ __align__(16) char smem_raw[];
    uint32_t a_s = smem_u32(smem_raw);
    uint32_t b_s = a_s + NSTAGE * TILE_BYTES;

    int tid = threadIdx.x, lane = tid & 31, wid = tid >> 5;
    int wm = wid & 1, wn = wid >> 1;
    int lrow = tid >> 2, lc8 = tid & 3;

    int kmax = (CMODE == 2) ? (m0 + 128) : K;
    int tot = kmax / KC;

    float acc[4][8][4];
    #pragma unroll
    for (int i = 0; i < 4; i++)
        #pragma unroll
        for (int j = 0; j < 8; j++)
            #pragma unroll
            for (int q = 0; q < 4; q++) acc[i][j][q] = 0.f;

    GEMM_MAINLOOP(A, B, K)

    int gr = lane >> 2, qc = (lane & 3) * 2;
    #pragma unroll
    for (int mi = 0; mi < 4; mi++) {
        #pragma unroll
        for (int half_ = 0; half_ < 2; half_++) {
            int m = m0 + wm * 64 + mi * 16 + gr + half_ * 8;
            #pragma unroll
            for (int ni = 0; ni < 8; ni++) {
                int n = n0 + wn * 64 + ni * 8 + qc;
                float v0 = acc[mi][ni][half_ * 2 + 0] * scale;
                float v1 = acc[mi][ni][half_ * 2 + 1] * scale;
                if (bias) { v0 += bias[n]; v1 += bias[n + 1]; }
                if (OUT16) {
                    *(uint32_t*)&Ch[(size_t)m * N + n] = pack_h2(v0, v1);
                } else {
                    *(float2*)&Cf[(size_t)m * N + n] = make_float2(v0, v1);
                }
            }
        }
    }
}

// ---------------------------------------------------------------------------
// merged QKV projection: grid.x = 24 (bx>>3 -> 0:Q 1:K 2:V), grid.y = 64.
// Q/K: +bias, +RoPE, fp16 [M,C]. V: +bias, transpose epilogue -> Vt [B,C,T].
// ---------------------------------------------------------------------------
__global__ void __launch_bounds__(128, 2) gemm_qkv(
    const __half* __restrict__ X,
    const __half* __restrict__ Wq, const __half* __restrict__ Wk,
    const __half* __restrict__ Wv,
    const float* __restrict__ bq, const float* __restrict__ bk,
    const float* __restrict__ bv,
    const float2* __restrict__ cs,
    __half* __restrict__ Q, __half* __restrict__ Kd, __half* __restrict__ Vt)
{
    int bx = blockIdx.x;
    int tgt = bx >> 3;
    int n0 = (bx & 7) * 128;
    int m0 = blockIdx.y * 128;

    const __half* B = (tgt == 0) ? Wq : (tgt == 1) ? Wk : Wv;
    const float* bias = (tgt == 0) ? bq : (tgt == 1) ? bk : bv;

    extern __shared__ __align__(16) char smem_raw[];
    uint32_t a_s = smem_u32(smem_raw);
    uint32_t b_s = a_s + NSTAGE * TILE_BYTES;

    int tid = threadIdx.x, lane = tid & 31, wid = tid >> 5;
    int wm = wid & 1, wn = wid >> 1;
    int lrow = tid >> 2, lc8 = tid & 3;
    int tot = CDIM / KC;

    float acc[4][8][4];
    #pragma unroll
    for (int i = 0; i < 4; i++)
        #pragma unroll
        for (int j = 0; j < 8; j++)
            #pragma unroll
            for (int q = 0; q < 4; q++) acc[i][j][q] = 0.f;

    GEMM_MAINLOOP(X, B, CDIM)

    int gr = lane >> 2, qc = (lane & 3) * 2;

    if (tgt < 2) {
        __half* Ch = (tgt == 0) ? Q : Kd;
        #pragma unroll
        for (int mi = 0; mi < 4; mi++) {
            #pragma unroll
            for (int half_ = 0; half_ < 2; half_++) {
                int m = m0 + wm * 64 + mi * 16 + gr + half_ * 8;
                int t = m & (TSEQ - 1);
                #pragma unroll
                for (int ni = 0; ni < 8; ni++) {
                    int n = n0 + wn * 64 + ni * 8 + qc;
                    float v0 = acc[mi][ni][half_ * 2 + 0] + bias[n];
                    float v1 = acc[mi][ni][half_ * 2 + 1] + bias[n + 1];
                    float2 sc = cs[(size_t)t * (CDIM / 2) + (n >> 1)];
                    float a = v0, b = v1;
                    v0 = a * sc.x - b * sc.y;
                    v1 = b * sc.x + a * sc.y;
                    *(uint32_t*)&Ch[(size_t)m * CDIM + n] = pack_h2(v0, v1);
                }
            }
        }
    } else {
        // V: transpose through smem, write Vt[z][n][t] coalesced along t.
        __syncthreads();                       // mainloop smem ring is dead now
        __half* tr = (__half*)smem_raw;        // 128 x LDT halfs = 34 KB
        #pragma unroll
        for (int mi = 0; mi < 4; mi++) {
            #pragma unroll
            for (int half_ = 0; half_ < 2; half_++) {
                int ml = wm * 64 + mi * 16 + gr + half_ * 8;
                #pragma unroll
                for (int ni = 0; ni < 8; ni++) {
                    int nl = wn * 64 + ni * 8 + qc;
                    float v0 = acc[mi][ni][half_ * 2 + 0] + bias[n0 + nl];
                    float v1 = acc[mi][ni][half_ * 2 + 1] + bias[n0 + nl + 1];
                    tr[nl * LDT + ml]       = __float2half_rn(v0);
                    tr[(nl + 1) * LDT + ml] = __float2half_rn(v1);
                }
            }
        }
        __syncthreads();
        int z = m0 / TSEQ, t0 = m0 & (TSEQ - 1);
        const uint4* src = (const uint4*)(tr + tid * LDT);
        uint4* dst = (uint4*)(Vt + (size_t)z * CDIM * TSEQ
                              + (size_t)(n0 + tid) * TSEQ + t0);
        #pragma unroll
        for (int i = 0; i < 16; i++) dst[i] = src[i];
    }
}

// ---------------------------------------------------------------------------
// fused pre-pass: convert x + 4 weights to fp16, build RoPE table.
// ---------------------------------------------------------------------------
#define XW4   (MTOT*CDIM/4)            // 2M float4 items
#define WW4   (CDIM*CDIM/4)            // 256K
#define CVT_ITEMS (XW4 + 4*WW4)        // 3M
#define ROPE_ITEMS (TSEQ*(CDIM/2))     // 1M
#define PRE_TOTAL (CVT_ITEMS + ROPE_ITEMS)
#define PRE_BLOCKS (PRE_TOTAL / (256*4))

__global__ void __launch_bounds__(256) prepass_k(
    const float4* __restrict__ x,
    const float4* __restrict__ Wq, const float4* __restrict__ Wk,
    const float4* __restrict__ Wv, const float4* __restrict__ Wf,
    __half* __restrict__ X16,
    __half* __restrict__ Wq16, __half* __restrict__ Wk16,
    __half* __restrict__ Wv16, __half* __restrict__ Wf16,
    float2* __restrict__ cs)
{
    int base = blockIdx.x * 256 + threadIdx.x;
    const int stride = PRE_BLOCKS * 256;
    #pragma unroll
    for (int it = 0; it < 4; it++) {
        int idx = base + it * stride;
        if (idx < CVT_ITEMS) {
            const float4* src;
            __half* dst;
            int off;
            if (idx < XW4) { src = x; dst = X16; off = idx; }
            else {
                int sub = idx - XW4;
                int w = sub / WW4;
                off = sub - w * WW4;
                src = (w == 0) ? Wq : (w == 1) ? Wk : (w == 2) ? Wv : Wf;
                dst = (w == 0) ? Wq16 : (w == 1) ? Wk16 : (w == 2) ? Wv16 : Wf16;
            }
            float4 v = src[off];
            *(uint2*)&dst[(size_t)off * 4] =
                make_uint2(pack_h2(v.x, v.y), pack_h2(v.z, v.w));
        } else {
            int r = idx - CVT_ITEMS;             // 0 .. 1M-1
            int t = r >> 9;
            int p = r & 511;
            float freq = exp2f(-(float)(2 * p) * (13.28771238f / (float)CDIM));
            float ang = (float)t * freq;
            float s, c;
            sincosf(ang, &s, &c);
            cs[r] = make_float2(c, s);
        }
    }
}

// causal softmax: fp32 scores (live prefix only) -> fp16 probs, zero-padded
// through the row's 128-block boundary. Dead float4 groups (>= kend) are
// skipped ENTIRELY — no loads, no exp, no stores (issue-bound kernel).
__global__ void __launch_bounds__(256) softmax_h_k(
    const float* __restrict__ S, __half* __restrict__ P)
{
    long row = blockIdx.x;
    long b = row >> 11;
    int  t = (int)(row & (TSEQ - 1));
    const float* p = S + (b << 22) + ((long)t << 11);
    __half* ph = P + (b << 22) + ((long)t << 11);
    int n = t + 1;
    int kend = ((t >> 7) + 1) << 7;
    int ng = kend >> 2;                  // live float4 groups in this row
    int tid = threadIdx.x;

    float4 v[2];
    float mx = -INFINITY;
    #pragma unroll
    for (int i = 0; i < 2; i++) {
        int g = tid + 256 * i;
        if (g < ng) {
            int base = g * 4;
            v[i] = *(const float4*)(p + base);
            float* f = (float*)&v[i];
            #pragma unroll
            for (int c = 0; c < 4; c++) {
                if (base + c >= n) f[c] = -INFINITY;
                mx = fmaxf(mx, f[c]);
            }
        }
    }
    __shared__ float red[8];
    #pragma unroll
    for (int o = 16; o; o >>= 1) mx = fmaxf(mx, __shfl_xor_sync(~0u, mx, o));
    if ((tid & 31) == 0) red[tid >> 5] = mx;
    __syncthreads();
    mx = red[0];
    #pragma unroll
    for (int k = 1; k < 8; k++) mx = fmaxf(mx, red[k]);
    __syncthreads();

    float sum = 0.f;
    #pragma unroll
    for (int i = 0; i < 2; i++) {
        if (tid + 256 * i < ng) {
            float* f = (float*)&v[i];
            #pragma unroll
            for (int c = 0; c < 4; c++) {
                float e = (f[c] == -INFINITY) ? 0.f : __expf(f[c] - mx);
                f[c] = e;
                sum += e;
            }
        }
    }
    #pragma unroll
    for (int o = 16; o; o >>= 1) sum += __shfl_xor_sync(~0u, sum, o);
    if ((tid & 31) == 0) red[tid >> 5] = sum;
    __syncthreads();
    sum = 0.f;
    #pragma unroll
    for (int k = 0; k < 8; k++) sum += red[k];
    float inv = 1.0f / sum;

    #pragma unroll
    for (int i = 0; i < 2; i++) {
        int g = tid + 256 * i;
        if (g < ng) {
            float* f = (float*)&v[i];
            *(uint2*)(ph + g * 4) =
                make_uint2(pack_h2(f[0] * inv, f[1] * inv),
                           pack_h2(f[2] * inv, f[3] * inv));
        }
    }
}

// ---------------------------------------------------------------------------
extern "C" void kernel_launch(void* const* d_in, const int* in_sizes, int n_in,
                              void* d_out, int out_size)
{
    const float* x  = (const float*)d_in[0];
    const float* Wq = (const float*)d_in[1];
    const float* bq = (const float*)d_in[2];
    const float* Wk = (const float*)d_in[3];
    const float* bk = (const float*)d_in[4];
    const float* Wv = (const float*)d_in[5];
    const float* bv = (const float*)d_in[6];
    const float* Wf = (const float*)d_in[7];
    const float* bf = (const float*)d_in[8];
    float* out = (float*)d_out;

    __half *X16,*Wq16,*Wk16,*Wv16,*Wf16,*Q16,*K16,*Vt,*P,*O16;
    float *S;
    float2* CS;
    cudaGetSymbolAddress((void**)&X16,  g_X16);
    cudaGetSymbolAddress((void**)&Wq16, g_Wq16);
    cudaGetSymbolAddress((void**)&Wk16, g_Wk16);
    cudaGetSymbolAddress((void**)&Wv16, g_Wv16);
    cudaGetSymbolAddress((void**)&Wf16, g_Wf16);
    cudaGetSymbolAddress((void**)&Q16,  g_Q16);
    cudaGetSymbolAddress((void**)&K16,  g_K16);
    cudaGetSymbolAddress((void**)&Vt,   g_Vt);
    cudaGetSymbolAddress((void**)&S,    g_S);
    cudaGetSymbolAddress((void**)&P,    g_P);
    cudaGetSymbolAddress((void**)&O16,  g_O16);
    cudaGetSymbolAddress((void**)&CS,   g_CS);

    cudaFuncSetAttribute(gemm_qkv,    cudaFuncAttributeMaxDynamicSharedMemorySize, SMEM_DYN);
    cudaFuncSetAttribute(gemm_h<1,0>, cudaFuncAttributeMaxDynamicSharedMemorySize, SMEM_DYN);
    cudaFuncSetAttribute(gemm_h<2,1>, cudaFuncAttributeMaxDynamicSharedMemorySize, SMEM_DYN);
    cudaFuncSetAttribute(gemm_h<0,0>, cudaFuncAttributeMaxDynamicSharedMemorySize, SMEM_DYN);

    dim3 gblk(128);
    dim3 blk(256);

    // launch 0: fused converts + rope table (4 items/thread)
    prepass_k<<<PRE_BLOCKS, blk>>>(
        (const float4*)x, (const float4*)Wq, (const float4*)Wk,
        (const float4*)Wv, (const float4*)Wf,
        X16, Wq16, Wk16, Wv16, Wf16, CS);

    // launch 1: merged Q/K/V projections (V written transposed)
    dim3 gQKV(24, MTOT / 128, 1);
    gemm_qkv<<<gQKV, gblk, SMEM_DYN>>>(X16, Wq16, Wk16, Wv16, bq, bk, bv, CS,
                                       Q16, K16, Vt);

    // launch 2: S = Q K^T / 32, triangular-packed causal grid (136 tiles)
    dim3 gS(136, 1, BSZ);
    gemm_h<1,0><<<gS, gblk, SMEM_DYN>>>(Q16, K16, nullptr, S, nullptr,
                                        TSEQ, CDIM,
                                        (long)TSEQ * CDIM, (long)TSEQ * CDIM,
                                        (long)TSEQ * TSEQ, 1.0f / 32.0f);

    // launch 3: softmax (live-prefix only)
    softmax_h_k<<<BSZ * TSEQ, blk>>>(S, P);

    // launch 4: O = P V (causal k-limit, heavy-first LPT order) -> fp16
    dim3 gPV(CDIM / 128, TSEQ / 128, BSZ);
    gemm_h<2,1><<<gPV, gblk, SMEM_DYN>>>(P, Vt, nullptr, nullptr, O16,
                                         CDIM, TSEQ,
                                         (long)TSEQ * TSEQ, (long)CDIM * TSEQ,
                                         (long)TSEQ * CDIM, 1.0f);

    // launch 5: out = O Wf^T + bf (fp32)
    dim3 gOut(CDIM / 128, MTOT / 128, 1);
    gemm_h<0,0><<<gOut, gblk, SMEM_DYN>>>(O16, Wf16, bf, out, nullptr,
                                          CDIM, CDIM, 0, 0, 0, 1.0f);
}